// round 4
// baseline (speedup 1.0000x reference)
#include <cuda_runtime.h>
#include <cuda_bf16.h>
#include <cstdint>

#define N_USERS 100000
#define N_ITEMS 50000
#define N_NODES 150000
#define EMB 64
#define N_EDGES 4000000
#define LN_EPS 1e-5f

typedef unsigned long long u64;

// ---------------- packed f32x2 helpers (sm_103a FFMA2) ----------------
__device__ __forceinline__ u64 pk2(float x, float y) {
    u64 r; asm("mov.b64 %0, {%1, %2};" : "=l"(r) : "f"(x), "f"(y)); return r;
}
__device__ __forceinline__ void upk2(u64 v, float& x, float& y) {
    asm("mov.b64 {%0, %1}, %2;" : "=f"(x), "=f"(y) : "l"(v));
}
__device__ __forceinline__ u64 ffma2(u64 a, u64 b, u64 c) {
    u64 d; asm("fma.rn.f32x2 %0, %1, %2, %3;" : "=l"(d) : "l"(a), "l"(b), "l"(c)); return d;
}
// vectorized global reduction (PTX ISA 8.1+, sm_90+)
__device__ __forceinline__ void red_add_v4(float* p, float4 v) {
    asm volatile("red.global.add.v4.f32 [%0], {%1, %2, %3, %4};"
                 :: "l"(p), "f"(v.x), "f"(v.y), "f"(v.z), "f"(v.w) : "memory");
}

// ---------------- scratch (device globals; no allocation allowed) ----------------
__device__ float g_A[N_NODES * EMB];     // all_emb (layer-0)
__device__ float g_B[N_NODES * EMB];     // spmm layer-1 output
__device__ float g_C[N_NODES * EMB];     // spmm layer-2 output
__device__ float g_m0[N_ITEMS * EMB];
__device__ float g_m1[N_ITEMS * EMB];
__device__ float g_usum[EMB];            // sum of user_emb rows
__device__ float g_umsum[EMB];           // sum of encoded modal_feat2 rows

// =====================================================================
// encode: out = LeakyReLU(LayerNorm(X @ W + b), 0.2)
// Block: 256 thr = 8 warps, 128 rows/block.
// Warp: 2 half-warps x 8 rows each; lane-quarter lq owns 4 output cols.
// Register tile: 8 rows x 4 cols -> 16 FMA2 per (1 LDS.128 W + 8 LDS x).
// =====================================================================
__global__ void encode_kernel(const float* __restrict__ X,
                              const float* __restrict__ W,
                              const float* __restrict__ bias,
                              const float* __restrict__ gamma,
                              const float* __restrict__ beta,
                              float* __restrict__ out,       // may be null
                              float* __restrict__ sum_out,   // may be null
                              int rows, int F)
{
    __shared__ float xs[128 * 32];
    __shared__ float ws[32 * 64];
    __shared__ float ssum[64];

    const int tid  = threadIdx.x;
    if (sum_out && tid < 64) ssum[tid] = 0.f;

    const int warp = tid >> 5;
    const int lane = tid & 31;
    const int half = lane >> 4;
    const int lq   = lane & 15;
    const unsigned hmask = 0xFFFFu << (half * 16);

    const int rowLocal0 = warp * 16 + half * 8;          // local base row (8 rows)
    const int rowG0     = blockIdx.x * 128 + rowLocal0;  // global base row
    const int c0        = lq * 4;                        // 4 output cols

    u64 acc[8][2];
#pragma unroll
    for (int r = 0; r < 8; r++) { acc[r][0] = pk2(0.f, 0.f); acc[r][1] = pk2(0.f, 0.f); }

    for (int kc = 0; kc < F; kc += 32) {
        __syncthreads();
        // stage X tile: 128 rows x 32 k (1024 float4)
        for (int t = tid; t < 1024; t += 256) {
            int r  = t >> 3;
            int j4 = (t & 7) << 2;
            int gr = blockIdx.x * 128 + r;
            float4 v = make_float4(0.f, 0.f, 0.f, 0.f);
            if (gr < rows) v = *(const float4*)&X[(size_t)gr * F + kc + j4];
            *(float4*)&xs[r * 32 + j4] = v;
        }
        // stage W tile: contiguous 32x64 chunk
        for (int t = tid; t < 512; t += 256)
            *(float4*)&ws[t * 4] = *(const float4*)&W[(size_t)kc * 64 + t * 4];
        __syncthreads();

#pragma unroll 8
        for (int j = 0; j < 32; j++) {
            float4 wv = *(const float4*)&ws[j * 64 + c0];
            u64 w01 = pk2(wv.x, wv.y);
            u64 w23 = pk2(wv.z, wv.w);
#pragma unroll
            for (int r = 0; r < 8; r++) {
                float xv = xs[(rowLocal0 + r) * 32 + j];   // half-warp broadcast
                u64 xx = pk2(xv, xv);
                acc[r][0] = ffma2(xx, w01, acc[r][0]);
                acc[r][1] = ffma2(xx, w23, acc[r][1]);
            }
        }
    }

    // epilogue: bias + LN(64) + LeakyReLU(0.2)
    const float4 b4  = *(const float4*)&bias[c0];
    const float4 gm4 = *(const float4*)&gamma[c0];
    const float4 bt4 = *(const float4*)&beta[c0];
    float ps0 = 0.f, ps1 = 0.f, ps2 = 0.f, ps3 = 0.f;

#pragma unroll
    for (int r = 0; r < 8; r++) {
        int gr = rowG0 + r;
        if (gr < rows) {                 // uniform across half-warp
            float y0, y1, y2, y3;
            upk2(acc[r][0], y0, y1); upk2(acc[r][1], y2, y3);
            y0 += b4.x; y1 += b4.y; y2 += b4.z; y3 += b4.w;
            float s = y0 + y1 + y2 + y3;
#pragma unroll
            for (int o = 1; o < 16; o <<= 1) s += __shfl_xor_sync(hmask, s, o);
            float mu = s * (1.f / 64.f);
            float d0 = y0 - mu, d1 = y1 - mu, d2 = y2 - mu, d3 = y3 - mu;
            float q = d0 * d0 + d1 * d1 + d2 * d2 + d3 * d3;
#pragma unroll
            for (int o = 1; o < 16; o <<= 1) q += __shfl_xor_sync(hmask, q, o);
            float rs = rsqrtf(q * (1.f / 64.f) + LN_EPS);
            float z0 = d0 * rs * gm4.x + bt4.x;
            float z1 = d1 * rs * gm4.y + bt4.y;
            float z2 = d2 * rs * gm4.z + bt4.z;
            float z3 = d3 * rs * gm4.w + bt4.w;
            z0 = z0 > 0.f ? z0 : 0.2f * z0;
            z1 = z1 > 0.f ? z1 : 0.2f * z1;
            z2 = z2 > 0.f ? z2 : 0.2f * z2;
            z3 = z3 > 0.f ? z3 : 0.2f * z3;
            if (out) *(float4*)&out[(size_t)gr * 64 + c0] = make_float4(z0, z1, z2, z3);
            if (sum_out) { ps0 += z0; ps1 += z1; ps2 += z2; ps3 += z3; }
        }
    }

    if (sum_out) {
        atomicAdd(&ssum[c0 + 0], ps0);
        atomicAdd(&ssum[c0 + 1], ps1);
        atomicAdd(&ssum[c0 + 2], ps2);
        atomicAdd(&ssum[c0 + 3], ps3);
        __syncthreads();
        if (tid < 64) atomicAdd(&sum_out[tid], ssum[tid]);
    }
}

// column sum of [rows,64] -> sum[64]
__global__ void colsum_kernel(const float* __restrict__ X, float* __restrict__ sum, int rows)
{
    __shared__ float ss[64];
    int tid = threadIdx.x;
    if (tid < 64) ss[tid] = 0.f;
    __syncthreads();
    int c = tid & 63;
    int g = tid >> 6;              // 4 row groups
    int base = blockIdx.x * 2048;
    int end = min(base + 2048, rows);
    float s = 0.f;
    for (int r = base + g; r < end; r += 4) s += X[(size_t)r * 64 + c];
    atomicAdd(&ss[c], s);
    __syncthreads();
    if (tid < 64) atomicAdd(&sum[tid], ss[tid]);
}

// copy users part of all_emb
__global__ void copy_users_kernel(const float* __restrict__ user_emb, float* __restrict__ A)
{
    int i = blockIdx.x * blockDim.x + threadIdx.x;   // float4 index
    const int n4 = N_USERS * EMB / 4;
    if (i < n4) ((float4*)A)[i] = ((const float4*)user_emb)[i];
}

// per-item modal attention + weighted combine. warp per item, lane -> cols (2l, 2l+1)
__global__ void attn_kernel(const float* __restrict__ item_emb,
                            const float* __restrict__ W1, const float* __restrict__ b1,
                            const float* __restrict__ W2, const float* __restrict__ b2,
                            const float* __restrict__ usum, const float* __restrict__ umsum,
                            const float* __restrict__ m0buf, const float* __restrict__ m1buf,
                            float* __restrict__ A)
{
    int warp = threadIdx.x >> 5;
    int lane = threadIdx.x & 31;
    int i = blockIdx.x * 8 + warp;
    if (i >= N_ITEMS) return;

    const float invU = 1.f / (float)N_USERS;
    float2 u, e;
    u.x = usum[2 * lane] * invU;  u.y = usum[2 * lane + 1] * invU;
    e = *(const float2*)&item_emb[(size_t)i * 64 + 2 * lane];

    u64 h = pk2(0.f, 0.f);
#pragma unroll 8
    for (int j = 0; j < 32; j++) {
        float ua = __shfl_sync(0xFFFFFFFFu, u.x, j);
        float ub = __shfl_sync(0xFFFFFFFFu, u.y, j);
        float2 wA = *(const float2*)&W1[(size_t)(2 * j) * 64 + 2 * lane];
        float2 wB = *(const float2*)&W1[(size_t)(2 * j + 1) * 64 + 2 * lane];
        h = ffma2(pk2(ua, ua), pk2(wA.x, wA.y), h);
        h = ffma2(pk2(ub, ub), pk2(wB.x, wB.y), h);
    }
#pragma unroll 8
    for (int j = 0; j < 32; j++) {
        float ea = __shfl_sync(0xFFFFFFFFu, e.x, j);
        float eb = __shfl_sync(0xFFFFFFFFu, e.y, j);
        float2 wA = *(const float2*)&W1[(size_t)(64 + 2 * j) * 64 + 2 * lane];
        float2 wB = *(const float2*)&W1[(size_t)(64 + 2 * j + 1) * 64 + 2 * lane];
        h = ffma2(pk2(ea, ea), pk2(wA.x, wA.y), h);
        h = ffma2(pk2(eb, eb), pk2(wB.x, wB.y), h);
    }
    float h0, h1;
    upk2(h, h0, h1);
    h0 = tanhf(h0 + b1[2 * lane]);
    h1 = tanhf(h1 + b1[2 * lane + 1]);

    float p0 = h0 * W2[(2 * lane) * 3 + 0] + h1 * W2[(2 * lane + 1) * 3 + 0];
    float p1 = h0 * W2[(2 * lane) * 3 + 1] + h1 * W2[(2 * lane + 1) * 3 + 1];
    float p2 = h0 * W2[(2 * lane) * 3 + 2] + h1 * W2[(2 * lane + 1) * 3 + 2];
#pragma unroll
    for (int o = 1; o < 32; o <<= 1) {
        p0 += __shfl_xor_sync(0xFFFFFFFFu, p0, o);
        p1 += __shfl_xor_sync(0xFFFFFFFFu, p1, o);
        p2 += __shfl_xor_sync(0xFFFFFFFFu, p2, o);
    }
    p0 += b2[0]; p1 += b2[1]; p2 += b2[2];
    float mx = fmaxf(p0, fmaxf(p1, p2));
    float e0 = expf(p0 - mx), e1 = expf(p1 - mx), e2 = expf(p2 - mx);
    float inv = 1.f / (e0 + e1 + e2);
    float w0 = e0 * inv, w1 = e1 * inv, w2 = e2 * inv;

    float2 m0v = *(const float2*)&m0buf[(size_t)i * 64 + 2 * lane];
    float2 m1v = *(const float2*)&m1buf[(size_t)i * 64 + 2 * lane];
    float m2x = umsum[2 * lane] * invU;
    float m2y = umsum[2 * lane + 1] * invU;

    float2 res;
    res.x = e.x + w0 * m0v.x + w1 * m1v.x + w2 * m2x;
    res.y = e.y + w0 * m0v.y + w1 * m1v.y + w2 * m2y;
    *(float2*)&A[(size_t)(N_USERS + i) * 64 + 2 * lane] = res;
}

// =====================================================================
// COO SpMM: dst[row] += val * src[col].
// 256 threads stage 128 edges' (row,col,val) via 96 vector LDGs, then
// 16 edge-slots x 16 lanes do 8x (LDG.128 gather + red.v4 scatter) each.
// Metadata read via broadcast LDS (conflict-free, N=1).
// =====================================================================
#define SPMM_EPB 128
__global__ void spmm_kernel(const float* __restrict__ src, float* __restrict__ dst,
                            const float* __restrict__ vals,
                            const int* __restrict__ rows, const int* __restrict__ cols)
{
    __shared__ int   s_row[SPMM_EPB];
    __shared__ int   s_col[SPMM_EPB];
    __shared__ float s_val[SPMM_EPB];

    const int tid = threadIdx.x;
    const int e0  = blockIdx.x * SPMM_EPB;

    // stage metadata with vector loads: 3 segments x 32 threads x int4/float4
    if (tid < 96) {
        int seg = tid >> 5;            // 0: cols, 1: rows, 2: vals
        int q   = (tid & 31) << 2;     // element offset (0..124, step 4)
        int e   = e0 + q;
        if (e + 3 < N_EDGES) {
            if (seg == 0)      *(int4*)  &s_col[q] = *(const int4*)  &cols[e];
            else if (seg == 1) *(int4*)  &s_row[q] = *(const int4*)  &rows[e];
            else               *(float4*)&s_val[q] = *(const float4*)&vals[e];
        } else {
            for (int k = 0; k < 4; k++) {
                int ee = e + k;
                if (seg == 0)      s_col[q + k] = (ee < N_EDGES) ? cols[ee] : 0;
                else if (seg == 1) s_row[q + k] = (ee < N_EDGES) ? rows[ee] : 0;
                else               s_val[q + k] = (ee < N_EDGES) ? vals[ee] : 0.f;
            }
        }
    }
    __syncthreads();

    const int slot = tid >> 4;          // 16 concurrent edge-slots
    const int c    = (tid & 15) << 2;   // 4-float chunk within the 64-wide row

#pragma unroll
    for (int i = 0; i < SPMM_EPB / 16; i++) {
        int idx = slot + i * 16;
        int e = e0 + idx;
        if (e < N_EDGES) {
            int   col = s_col[idx];     // broadcast LDS (conflict-free)
            int   row = s_row[idx];
            float v   = s_val[idx];
            float4 x = *(const float4*)&src[(size_t)col * 64 + c];
            red_add_v4(&dst[(size_t)row * 64 + c],
                       make_float4(x.x * v, x.y * v, x.z * v, x.w * v));
        }
    }
}

// out = (A + B + C) / 3
__global__ void finalize_kernel(const float* __restrict__ A, const float* __restrict__ B,
                                const float* __restrict__ C, float* __restrict__ out)
{
    int i = blockIdx.x * blockDim.x + threadIdx.x;     // float4 index
    const int n4 = N_NODES * EMB / 4;
    if (i >= n4) return;
    float4 a = ((const float4*)A)[i];
    float4 b = ((const float4*)B)[i];
    float4 c = ((const float4*)C)[i];
    const float s = 1.f / 3.f;
    ((float4*)out)[i] = make_float4((a.x + b.x + c.x) * s, (a.y + b.y + c.y) * s,
                                    (a.z + b.z + c.z) * s, (a.w + b.w + c.w) * s);
}

extern "C" void kernel_launch(void* const* d_in, const int* in_sizes, int n_in,
                              void* d_out, int out_size)
{
    const float* user_emb = (const float*)d_in[0];
    const float* item_emb = (const float*)d_in[1];
    const float* mf0 = (const float*)d_in[2];
    const float* mf1 = (const float*)d_in[3];
    const float* mf2 = (const float*)d_in[4];
    const float* W0  = (const float*)d_in[5];
    const float* b0  = (const float*)d_in[6];
    const float* g0  = (const float*)d_in[7];
    const float* be0 = (const float*)d_in[8];
    const float* W1  = (const float*)d_in[9];
    const float* b1  = (const float*)d_in[10];
    const float* g1  = (const float*)d_in[11];
    const float* be1 = (const float*)d_in[12];
    const float* W2  = (const float*)d_in[13];
    const float* b2  = (const float*)d_in[14];
    const float* g2  = (const float*)d_in[15];
    const float* be2 = (const float*)d_in[16];
    const float* aW1 = (const float*)d_in[17];
    const float* ab1 = (const float*)d_in[18];
    const float* aW2 = (const float*)d_in[19];
    const float* ab2 = (const float*)d_in[20];
    const float* adj_vals = (const float*)d_in[21];
    const int*   adj_rows = (const int*)d_in[22];
    const int*   adj_cols = (const int*)d_in[23];

    float *pA, *pB, *pC, *pM0, *pM1, *pUS, *pUM;
    cudaGetSymbolAddress((void**)&pA, g_A);
    cudaGetSymbolAddress((void**)&pB, g_B);
    cudaGetSymbolAddress((void**)&pC, g_C);
    cudaGetSymbolAddress((void**)&pM0, g_m0);
    cudaGetSymbolAddress((void**)&pM1, g_m1);
    cudaGetSymbolAddress((void**)&pUS, g_usum);
    cudaGetSymbolAddress((void**)&pUM, g_umsum);

    cudaMemsetAsync(pB, 0, (size_t)N_NODES * EMB * sizeof(float));
    cudaMemsetAsync(pC, 0, (size_t)N_NODES * EMB * sizeof(float));
    cudaMemsetAsync(pUS, 0, EMB * sizeof(float));
    cudaMemsetAsync(pUM, 0, EMB * sizeof(float));

    // encoders
    encode_kernel<<<(N_ITEMS + 127) / 128, 256>>>(mf0, W0, b0, g0, be0, pM0, nullptr, N_ITEMS, 768);
    encode_kernel<<<(N_ITEMS + 127) / 128, 256>>>(mf1, W1, b1, g1, be1, pM1, nullptr, N_ITEMS, 384);
    encode_kernel<<<(N_USERS + 127) / 128, 256>>>(mf2, W2, b2, g2, be2, nullptr, pUM, N_USERS, 128);

    // mean of raw user embeddings
    colsum_kernel<<<(N_USERS + 2047) / 2048, 256>>>(user_emb, pUS, N_USERS);

    // assemble all_emb
    copy_users_kernel<<<(N_USERS * EMB / 4 + 255) / 256, 256>>>(user_emb, pA);
    attn_kernel<<<(N_ITEMS + 7) / 8, 256>>>(item_emb, aW1, ab1, aW2, ab2,
                                            pUS, pUM, pM0, pM1, pA);

    // 2 propagation layers
    const int spmm_blocks = (N_EDGES + SPMM_EPB - 1) / SPMM_EPB;
    spmm_kernel<<<spmm_blocks, 256>>>(pA, pB, adj_vals, adj_rows, adj_cols);
    spmm_kernel<<<spmm_blocks, 256>>>(pB, pC, adj_vals, adj_rows, adj_cols);

    finalize_kernel<<<(N_NODES * EMB / 4 + 255) / 256, 256>>>(pA, pB, pC, (float*)d_out);
}

// round 5
// speedup vs baseline: 1.1728x; 1.1728x over previous
#include <cuda_runtime.h>
#include <cuda_bf16.h>
#include <cstdint>

#define N_USERS 100000
#define N_ITEMS 50000
#define N_NODES 150000
#define EMB 64
#define N_EDGES 4000000
#define LN_EPS 1e-5f
#define NSCAN_BLOCKS ((N_NODES + 1023) / 1024)   // 147

typedef unsigned long long u64;

// ---------------- packed f32x2 helpers (sm_103a FFMA2) ----------------
__device__ __forceinline__ u64 pk2(float x, float y) {
    u64 r; asm("mov.b64 %0, {%1, %2};" : "=l"(r) : "f"(x), "f"(y)); return r;
}
__device__ __forceinline__ void upk2(u64 v, float& x, float& y) {
    asm("mov.b64 {%0, %1}, %2;" : "=f"(x), "=f"(y) : "l"(v));
}
__device__ __forceinline__ u64 ffma2(u64 a, u64 b, u64 c) {
    u64 d; asm("fma.rn.f32x2 %0, %1, %2, %3;" : "=l"(d) : "l"(a), "l"(b), "l"(c)); return d;
}

// ---------------- scratch (device globals; no allocation allowed) ----------------
__device__ float g_A[N_NODES * EMB];     // all_emb (layer-0)
__device__ float g_B[N_NODES * EMB];     // spmm layer-1 output
__device__ float g_C[N_NODES * EMB];     // spmm layer-2 output
__device__ float g_m0[N_ITEMS * EMB];
__device__ float g_m1[N_ITEMS * EMB];
__device__ float g_usum[EMB];            // sum of user_emb rows
__device__ float g_umsum[EMB];           // sum of encoded modal_feat2 rows
// CSR build scratch
__device__ int   g_cnt[N_NODES];
__device__ int   g_rowptr[N_NODES + 1];
__device__ int   g_cur[N_NODES];
__device__ int   g_bsums[NSCAN_BLOCKS];
__device__ int2  g_epack[N_EDGES];       // (col, val-as-int) sorted by row

// =====================================================================
// encode: out = LeakyReLU(LayerNorm(X @ W + b), 0.2)
// =====================================================================
__global__ void encode_kernel(const float* __restrict__ X,
                              const float* __restrict__ W,
                              const float* __restrict__ bias,
                              const float* __restrict__ gamma,
                              const float* __restrict__ beta,
                              float* __restrict__ out,       // may be null
                              float* __restrict__ sum_out,   // may be null
                              int rows, int F)
{
    __shared__ float xs[128 * 32];
    __shared__ float ws[32 * 64];
    __shared__ float ssum[64];

    const int tid  = threadIdx.x;
    if (sum_out && tid < 64) ssum[tid] = 0.f;

    const int warp = tid >> 5;
    const int lane = tid & 31;
    const int half = lane >> 4;
    const int lq   = lane & 15;
    const unsigned hmask = 0xFFFFu << (half * 16);

    const int rowLocal0 = warp * 16 + half * 8;
    const int rowG0     = blockIdx.x * 128 + rowLocal0;
    const int c0        = lq * 4;

    u64 acc[8][2];
#pragma unroll
    for (int r = 0; r < 8; r++) { acc[r][0] = pk2(0.f, 0.f); acc[r][1] = pk2(0.f, 0.f); }

    for (int kc = 0; kc < F; kc += 32) {
        __syncthreads();
        for (int t = tid; t < 1024; t += 256) {
            int r  = t >> 3;
            int j4 = (t & 7) << 2;
            int gr = blockIdx.x * 128 + r;
            float4 v = make_float4(0.f, 0.f, 0.f, 0.f);
            if (gr < rows) v = *(const float4*)&X[(size_t)gr * F + kc + j4];
            *(float4*)&xs[r * 32 + j4] = v;
        }
        for (int t = tid; t < 512; t += 256)
            *(float4*)&ws[t * 4] = *(const float4*)&W[(size_t)kc * 64 + t * 4];
        __syncthreads();

#pragma unroll 8
        for (int j = 0; j < 32; j++) {
            float4 wv = *(const float4*)&ws[j * 64 + c0];
            u64 w01 = pk2(wv.x, wv.y);
            u64 w23 = pk2(wv.z, wv.w);
#pragma unroll
            for (int r = 0; r < 8; r++) {
                float xv = xs[(rowLocal0 + r) * 32 + j];
                u64 xx = pk2(xv, xv);
                acc[r][0] = ffma2(xx, w01, acc[r][0]);
                acc[r][1] = ffma2(xx, w23, acc[r][1]);
            }
        }
    }

    const float4 b4  = *(const float4*)&bias[c0];
    const float4 gm4 = *(const float4*)&gamma[c0];
    const float4 bt4 = *(const float4*)&beta[c0];
    float ps0 = 0.f, ps1 = 0.f, ps2 = 0.f, ps3 = 0.f;

#pragma unroll
    for (int r = 0; r < 8; r++) {
        int gr = rowG0 + r;
        if (gr < rows) {
            float y0, y1, y2, y3;
            upk2(acc[r][0], y0, y1); upk2(acc[r][1], y2, y3);
            y0 += b4.x; y1 += b4.y; y2 += b4.z; y3 += b4.w;
            float s = y0 + y1 + y2 + y3;
#pragma unroll
            for (int o = 1; o < 16; o <<= 1) s += __shfl_xor_sync(hmask, s, o);
            float mu = s * (1.f / 64.f);
            float d0 = y0 - mu, d1 = y1 - mu, d2 = y2 - mu, d3 = y3 - mu;
            float q = d0 * d0 + d1 * d1 + d2 * d2 + d3 * d3;
#pragma unroll
            for (int o = 1; o < 16; o <<= 1) q += __shfl_xor_sync(hmask, q, o);
            float rs = rsqrtf(q * (1.f / 64.f) + LN_EPS);
            float z0 = d0 * rs * gm4.x + bt4.x;
            float z1 = d1 * rs * gm4.y + bt4.y;
            float z2 = d2 * rs * gm4.z + bt4.z;
            float z3 = d3 * rs * gm4.w + bt4.w;
            z0 = z0 > 0.f ? z0 : 0.2f * z0;
            z1 = z1 > 0.f ? z1 : 0.2f * z1;
            z2 = z2 > 0.f ? z2 : 0.2f * z2;
            z3 = z3 > 0.f ? z3 : 0.2f * z3;
            if (out) *(float4*)&out[(size_t)gr * 64 + c0] = make_float4(z0, z1, z2, z3);
            if (sum_out) { ps0 += z0; ps1 += z1; ps2 += z2; ps3 += z3; }
        }
    }

    if (sum_out) {
        atomicAdd(&ssum[c0 + 0], ps0);
        atomicAdd(&ssum[c0 + 1], ps1);
        atomicAdd(&ssum[c0 + 2], ps2);
        atomicAdd(&ssum[c0 + 3], ps3);
        __syncthreads();
        if (tid < 64) atomicAdd(&sum_out[tid], ssum[tid]);
    }
}

// column sum of [rows,64] -> sum[64]; 512 rows per block
__global__ void colsum_kernel(const float* __restrict__ X, float* __restrict__ sum, int rows)
{
    __shared__ float ss[64];
    int tid = threadIdx.x;
    if (tid < 64) ss[tid] = 0.f;
    __syncthreads();
    int c = tid & 63;
    int g = tid >> 6;              // 4 row groups
    int base = blockIdx.x * 512;
    int end = min(base + 512, rows);
    float s = 0.f;
    for (int r = base + g; r < end; r += 4) s += X[(size_t)r * 64 + c];
    atomicAdd(&ss[c], s);
    __syncthreads();
    if (tid < 64) atomicAdd(&sum[tid], ss[tid]);
}

__global__ void copy_users_kernel(const float* __restrict__ user_emb, float* __restrict__ A)
{
    int i = blockIdx.x * blockDim.x + threadIdx.x;
    const int n4 = N_USERS * EMB / 4;
    if (i < n4) ((float4*)A)[i] = ((const float4*)user_emb)[i];
}

// per-item modal attention + weighted combine
__global__ void attn_kernel(const float* __restrict__ item_emb,
                            const float* __restrict__ W1, const float* __restrict__ b1,
                            const float* __restrict__ W2, const float* __restrict__ b2,
                            const float* __restrict__ usum, const float* __restrict__ umsum,
                            const float* __restrict__ m0buf, const float* __restrict__ m1buf,
                            float* __restrict__ A)
{
    int warp = threadIdx.x >> 5;
    int lane = threadIdx.x & 31;
    int i = blockIdx.x * 8 + warp;
    if (i >= N_ITEMS) return;

    const float invU = 1.f / (float)N_USERS;
    float2 u, e;
    u.x = usum[2 * lane] * invU;  u.y = usum[2 * lane + 1] * invU;
    e = *(const float2*)&item_emb[(size_t)i * 64 + 2 * lane];

    u64 h = pk2(0.f, 0.f);
#pragma unroll 8
    for (int j = 0; j < 32; j++) {
        float ua = __shfl_sync(0xFFFFFFFFu, u.x, j);
        float ub = __shfl_sync(0xFFFFFFFFu, u.y, j);
        float2 wA = *(const float2*)&W1[(size_t)(2 * j) * 64 + 2 * lane];
        float2 wB = *(const float2*)&W1[(size_t)(2 * j + 1) * 64 + 2 * lane];
        h = ffma2(pk2(ua, ua), pk2(wA.x, wA.y), h);
        h = ffma2(pk2(ub, ub), pk2(wB.x, wB.y), h);
    }
#pragma unroll 8
    for (int j = 0; j < 32; j++) {
        float ea = __shfl_sync(0xFFFFFFFFu, e.x, j);
        float eb = __shfl_sync(0xFFFFFFFFu, e.y, j);
        float2 wA = *(const float2*)&W1[(size_t)(64 + 2 * j) * 64 + 2 * lane];
        float2 wB = *(const float2*)&W1[(size_t)(64 + 2 * j + 1) * 64 + 2 * lane];
        h = ffma2(pk2(ea, ea), pk2(wA.x, wA.y), h);
        h = ffma2(pk2(eb, eb), pk2(wB.x, wB.y), h);
    }
    float h0, h1;
    upk2(h, h0, h1);
    h0 = tanhf(h0 + b1[2 * lane]);
    h1 = tanhf(h1 + b1[2 * lane + 1]);

    float p0 = h0 * W2[(2 * lane) * 3 + 0] + h1 * W2[(2 * lane + 1) * 3 + 0];
    float p1 = h0 * W2[(2 * lane) * 3 + 1] + h1 * W2[(2 * lane + 1) * 3 + 1];
    float p2 = h0 * W2[(2 * lane) * 3 + 2] + h1 * W2[(2 * lane + 1) * 3 + 2];
#pragma unroll
    for (int o = 1; o < 32; o <<= 1) {
        p0 += __shfl_xor_sync(0xFFFFFFFFu, p0, o);
        p1 += __shfl_xor_sync(0xFFFFFFFFu, p1, o);
        p2 += __shfl_xor_sync(0xFFFFFFFFu, p2, o);
    }
    p0 += b2[0]; p1 += b2[1]; p2 += b2[2];
    float mx = fmaxf(p0, fmaxf(p1, p2));
    float e0 = expf(p0 - mx), e1 = expf(p1 - mx), e2 = expf(p2 - mx);
    float inv = 1.f / (e0 + e1 + e2);
    float w0 = e0 * inv, w1 = e1 * inv, w2 = e2 * inv;

    float2 m0v = *(const float2*)&m0buf[(size_t)i * 64 + 2 * lane];
    float2 m1v = *(const float2*)&m1buf[(size_t)i * 64 + 2 * lane];
    float m2x = umsum[2 * lane] * invU;
    float m2y = umsum[2 * lane + 1] * invU;

    float2 res;
    res.x = e.x + w0 * m0v.x + w1 * m1v.x + w2 * m2x;
    res.y = e.y + w0 * m0v.y + w1 * m1v.y + w2 * m2y;
    *(float2*)&A[(size_t)(N_USERS + i) * 64 + 2 * lane] = res;
}

// ================= CSR build (counting sort by row) =================
__global__ void hist_kernel(const int* __restrict__ rows, int* __restrict__ cnt)
{
    int e = blockIdx.x * blockDim.x + threadIdx.x;
    if (e < N_EDGES) atomicAdd(&cnt[__ldg(&rows[e])], 1);
}

// per-block inclusive scan (1024 elems); writes rowptr[i+1] and block sums
__global__ void scan1_kernel(const int* __restrict__ cnt, int* __restrict__ rowptr,
                             int* __restrict__ bsums)
{
    __shared__ int sh[1024];
    int i = blockIdx.x * 1024 + threadIdx.x;
    sh[threadIdx.x] = (i < N_NODES) ? cnt[i] : 0;
    __syncthreads();
#pragma unroll
    for (int off = 1; off < 1024; off <<= 1) {
        int t = (threadIdx.x >= off) ? sh[threadIdx.x - off] : 0;
        __syncthreads();
        sh[threadIdx.x] += t;
        __syncthreads();
    }
    if (i < N_NODES) rowptr[i + 1] = sh[threadIdx.x];
    if (threadIdx.x == 1023) bsums[blockIdx.x] = sh[1023];
}

// serial exclusive scan of block sums (147 values)
__global__ void scan2_kernel(int* __restrict__ bsums)
{
    if (threadIdx.x == 0 && blockIdx.x == 0) {
        int acc = 0;
        for (int k = 0; k < NSCAN_BLOCKS; k++) { int t = bsums[k]; bsums[k] = acc; acc += t; }
    }
}

__global__ void scan3_kernel(int* __restrict__ rowptr, const int* __restrict__ bsums,
                             int* __restrict__ cur)
{
    int i = blockIdx.x * blockDim.x + threadIdx.x;
    if (i < N_NODES) rowptr[i + 1] += bsums[i >> 10];
    if (i == 0) rowptr[0] = 0;
}

__global__ void cursor_kernel(const int* __restrict__ rowptr, int* __restrict__ cur)
{
    int i = blockIdx.x * blockDim.x + threadIdx.x;
    if (i < N_NODES) cur[i] = rowptr[i];
}

__global__ void scatter_kernel(const int* __restrict__ rows, const int* __restrict__ cols,
                               const float* __restrict__ vals,
                               int* __restrict__ cur, int2* __restrict__ epack)
{
    int e = blockIdx.x * blockDim.x + threadIdx.x;
    if (e < N_EDGES) {
        int r = __ldg(&rows[e]);
        int pos = atomicAdd(&cur[r], 1);
        epack[pos] = make_int2(__ldg(&cols[e]), __float_as_int(__ldg(&vals[e])));
    }
}

// ================= CSR SpMM: one 16-lane group per output row ==========
__global__ void spmm_csr_kernel(const float* __restrict__ src, float* __restrict__ dst,
                                const int* __restrict__ rowptr,
                                const int2* __restrict__ epack)
{
    int row = blockIdx.x * 16 + (threadIdx.x >> 4);
    if (row >= N_NODES) return;
    const int c = (threadIdx.x & 15) << 2;

    int s = __ldg(&rowptr[row]);
    int e = __ldg(&rowptr[row + 1]);

    float4 acc = make_float4(0.f, 0.f, 0.f, 0.f);
    int j = s;
    for (; j + 1 < e; j += 2) {
        int2 m0 = __ldg(&epack[j]);
        int2 m1 = __ldg(&epack[j + 1]);
        float v0 = __int_as_float(m0.y);
        float v1 = __int_as_float(m1.y);
        float4 x0 = *(const float4*)&src[(size_t)m0.x * 64 + c];
        float4 x1 = *(const float4*)&src[(size_t)m1.x * 64 + c];
        acc.x = fmaf(x0.x, v0, acc.x); acc.y = fmaf(x0.y, v0, acc.y);
        acc.z = fmaf(x0.z, v0, acc.z); acc.w = fmaf(x0.w, v0, acc.w);
        acc.x = fmaf(x1.x, v1, acc.x); acc.y = fmaf(x1.y, v1, acc.y);
        acc.z = fmaf(x1.z, v1, acc.z); acc.w = fmaf(x1.w, v1, acc.w);
    }
    if (j < e) {
        int2 m0 = __ldg(&epack[j]);
        float v0 = __int_as_float(m0.y);
        float4 x0 = *(const float4*)&src[(size_t)m0.x * 64 + c];
        acc.x = fmaf(x0.x, v0, acc.x); acc.y = fmaf(x0.y, v0, acc.y);
        acc.z = fmaf(x0.z, v0, acc.z); acc.w = fmaf(x0.w, v0, acc.w);
    }
    *(float4*)&dst[(size_t)row * 64 + c] = acc;
}

// out = (A + B + C) / 3
__global__ void finalize_kernel(const float* __restrict__ A, const float* __restrict__ B,
                                const float* __restrict__ C, float* __restrict__ out)
{
    int i = blockIdx.x * blockDim.x + threadIdx.x;
    const int n4 = N_NODES * EMB / 4;
    if (i >= n4) return;
    float4 a = ((const float4*)A)[i];
    float4 b = ((const float4*)B)[i];
    float4 c = ((const float4*)C)[i];
    const float s = 1.f / 3.f;
    ((float4*)out)[i] = make_float4((a.x + b.x + c.x) * s, (a.y + b.y + c.y) * s,
                                    (a.z + b.z + c.z) * s, (a.w + b.w + c.w) * s);
}

extern "C" void kernel_launch(void* const* d_in, const int* in_sizes, int n_in,
                              void* d_out, int out_size)
{
    const float* user_emb = (const float*)d_in[0];
    const float* item_emb = (const float*)d_in[1];
    const float* mf0 = (const float*)d_in[2];
    const float* mf1 = (const float*)d_in[3];
    const float* mf2 = (const float*)d_in[4];
    const float* W0  = (const float*)d_in[5];
    const float* b0  = (const float*)d_in[6];
    const float* g0  = (const float*)d_in[7];
    const float* be0 = (const float*)d_in[8];
    const float* W1  = (const float*)d_in[9];
    const float* b1  = (const float*)d_in[10];
    const float* g1  = (const float*)d_in[11];
    const float* be1 = (const float*)d_in[12];
    const float* W2  = (const float*)d_in[13];
    const float* b2  = (const float*)d_in[14];
    const float* g2  = (const float*)d_in[15];
    const float* be2 = (const float*)d_in[16];
    const float* aW1 = (const float*)d_in[17];
    const float* ab1 = (const float*)d_in[18];
    const float* aW2 = (const float*)d_in[19];
    const float* ab2 = (const float*)d_in[20];
    const float* adj_vals = (const float*)d_in[21];
    const int*   adj_rows = (const int*)d_in[22];
    const int*   adj_cols = (const int*)d_in[23];

    float *pA, *pB, *pC, *pM0, *pM1, *pUS, *pUM;
    int *pCnt, *pRowptr, *pCur, *pBsums;
    int2 *pEpack;
    cudaGetSymbolAddress((void**)&pA, g_A);
    cudaGetSymbolAddress((void**)&pB, g_B);
    cudaGetSymbolAddress((void**)&pC, g_C);
    cudaGetSymbolAddress((void**)&pM0, g_m0);
    cudaGetSymbolAddress((void**)&pM1, g_m1);
    cudaGetSymbolAddress((void**)&pUS, g_usum);
    cudaGetSymbolAddress((void**)&pUM, g_umsum);
    cudaGetSymbolAddress((void**)&pCnt, g_cnt);
    cudaGetSymbolAddress((void**)&pRowptr, g_rowptr);
    cudaGetSymbolAddress((void**)&pCur, g_cur);
    cudaGetSymbolAddress((void**)&pBsums, g_bsums);
    cudaGetSymbolAddress((void**)&pEpack, g_epack);

    cudaMemsetAsync(pUS, 0, EMB * sizeof(float));
    cudaMemsetAsync(pUM, 0, EMB * sizeof(float));
    cudaMemsetAsync(pCnt, 0, N_NODES * sizeof(int));

    // CSR build (overlapping-independent of encoders, but same stream is fine)
    hist_kernel<<<(N_EDGES + 255) / 256, 256>>>(adj_rows, pCnt);

    // encoders
    encode_kernel<<<(N_ITEMS + 127) / 128, 256>>>(mf0, W0, b0, g0, be0, pM0, nullptr, N_ITEMS, 768);
    encode_kernel<<<(N_ITEMS + 127) / 128, 256>>>(mf1, W1, b1, g1, be1, pM1, nullptr, N_ITEMS, 384);
    encode_kernel<<<(N_USERS + 127) / 128, 256>>>(mf2, W2, b2, g2, be2, nullptr, pUM, N_USERS, 128);

    // CSR build continued
    scan1_kernel<<<NSCAN_BLOCKS, 1024>>>(pCnt, pRowptr, pBsums);
    scan2_kernel<<<1, 32>>>(pBsums);
    scan3_kernel<<<(N_NODES + 255) / 256, 256>>>(pRowptr, pBsums, pCur);
    cursor_kernel<<<(N_NODES + 255) / 256, 256>>>(pRowptr, pCur);
    scatter_kernel<<<(N_EDGES + 255) / 256, 256>>>(adj_rows, adj_cols, adj_vals, pCur, pEpack);

    // mean of raw user embeddings
    colsum_kernel<<<(N_USERS + 511) / 512, 256>>>(user_emb, pUS, N_USERS);

    // assemble all_emb
    copy_users_kernel<<<(N_USERS * EMB / 4 + 255) / 256, 256>>>(user_emb, pA);
    attn_kernel<<<(N_ITEMS + 7) / 8, 256>>>(item_emb, aW1, ab1, aW2, ab2,
                                            pUS, pUM, pM0, pM1, pA);

    // 2 propagation layers (CSR, atomic-free)
    const int spmm_blocks = (N_NODES + 15) / 16;
    spmm_csr_kernel<<<spmm_blocks, 256>>>(pA, pB, pRowptr, pEpack);
    spmm_csr_kernel<<<spmm_blocks, 256>>>(pB, pC, pRowptr, pEpack);

    finalize_kernel<<<(N_NODES * EMB / 4 + 255) / 256, 256>>>(pA, pB, pC, (float*)d_out);
}

// round 10
// speedup vs baseline: 1.6396x; 1.3980x over previous
#include <cuda_runtime.h>
#include <cuda_bf16.h>
#include <cstdint>

#define N_USERS 100000
#define N_ITEMS 50000
#define N_NODES 150000
#define EMB 64
#define N_EDGES 4000000
#define LN_EPS 1e-5f
#define NSCAN_BLOCKS ((N_NODES + 1023) / 1024)   // 147

// megakernel section sizes
#define NB_ENC2 782    // users encoder, F=128
#define NB_ENC0 391    // items encoder, F=768
#define NB_ENC1 391    // items encoder, F=384
#define NB_HIST 15625  // 4M edges / 256
#define NB_COLSUM 196  // 100000 rows / 512
#define NB_TOTAL (NB_ENC2 + NB_ENC0 + NB_ENC1 + NB_HIST + NB_COLSUM)

typedef unsigned long long u64;

// ---------------- packed f32x2 helpers (sm_103a FFMA2) ----------------
__device__ __forceinline__ u64 pk2(float x, float y) {
    u64 r; asm("mov.b64 %0, {%1, %2};" : "=l"(r) : "f"(x), "f"(y)); return r;
}
__device__ __forceinline__ void upk2(u64 v, float& x, float& y) {
    asm("mov.b64 {%0, %1}, %2;" : "=f"(x), "=f"(y) : "l"(v));
}
__device__ __forceinline__ u64 ffma2(u64 a, u64 b, u64 c) {
    u64 d; asm("fma.rn.f32x2 %0, %1, %2, %3;" : "=l"(d) : "l"(a), "l"(b), "l"(c)); return d;
}

// ---------------- scratch (device globals; no allocation allowed) ----------------
__device__ float g_Ai[N_ITEMS * EMB];    // items part of all_emb (users part = user_emb directly)
__device__ float g_B[N_NODES * EMB];     // spmm layer-1 output
__device__ float g_m0[N_ITEMS * EMB];
__device__ float g_m1[N_ITEMS * EMB];
__device__ float g_usum[EMB];
__device__ float g_umsum[EMB];
// CSR build scratch
__device__ int   g_cnt[N_NODES];
__device__ int   g_rowptr[N_NODES + 1];
__device__ int   g_cur[N_NODES];
__device__ int   g_bsums[NSCAN_BLOCKS];
__device__ int2  g_epack[N_EDGES];       // (col, val-as-int) sorted by row

// =====================================================================
// encode body: out = LeakyReLU(LayerNorm(X @ W + b), 0.2)
// 256 thr, 128 rows/block; half-warp owns 8 rows x (lane-quarter) 4 cols.
// Inner loop: per 4 k-steps -> 12 LDS.128 + 64 FFMA2.
// =====================================================================
__device__ __forceinline__ void encode_body(
    const float* __restrict__ X, const float* __restrict__ W,
    const float* __restrict__ bias, const float* __restrict__ gamma,
    const float* __restrict__ beta,
    float* __restrict__ out, float* __restrict__ sum_out,
    int rows, int F, int blk,
    float* xs /*128*32*/, float* ws /*32*64*/, float* ssum /*64*/)
{
    const int tid  = threadIdx.x;
    if (sum_out && tid < 64) ssum[tid] = 0.f;

    const int warp = tid >> 5;
    const int lane = tid & 31;
    const int half = lane >> 4;
    const int lq   = lane & 15;
    const unsigned hmask = 0xFFFFu << (half * 16);

    const int rowLocal0 = warp * 16 + half * 8;
    const int rowG0     = blk * 128 + rowLocal0;
    const int c0        = lq * 4;

    u64 acc[8][2];
#pragma unroll
    for (int r = 0; r < 8; r++) { acc[r][0] = pk2(0.f, 0.f); acc[r][1] = pk2(0.f, 0.f); }

    for (int kc = 0; kc < F; kc += 32) {
        __syncthreads();
        for (int t = tid; t < 1024; t += 256) {
            int r  = t >> 3;
            int j4 = (t & 7) << 2;
            int gr = blk * 128 + r;
            float4 v = make_float4(0.f, 0.f, 0.f, 0.f);
            if (gr < rows) v = *(const float4*)&X[(size_t)gr * F + kc + j4];
            *(float4*)&xs[r * 32 + j4] = v;
        }
        for (int t = tid; t < 512; t += 256)
            *(float4*)&ws[t * 4] = *(const float4*)&W[(size_t)kc * 64 + t * 4];
        __syncthreads();

#pragma unroll
        for (int j4 = 0; j4 < 8; j4++) {
            float4 w0 = *(const float4*)&ws[(j4 * 4 + 0) * 64 + c0];
            float4 w1 = *(const float4*)&ws[(j4 * 4 + 1) * 64 + c0];
            float4 w2 = *(const float4*)&ws[(j4 * 4 + 2) * 64 + c0];
            float4 w3 = *(const float4*)&ws[(j4 * 4 + 3) * 64 + c0];
            u64 wA0 = pk2(w0.x, w0.y), wB0 = pk2(w0.z, w0.w);
            u64 wA1 = pk2(w1.x, w1.y), wB1 = pk2(w1.z, w1.w);
            u64 wA2 = pk2(w2.x, w2.y), wB2 = pk2(w2.z, w2.w);
            u64 wA3 = pk2(w3.x, w3.y), wB3 = pk2(w3.z, w3.w);
#pragma unroll
            for (int r = 0; r < 8; r++) {
                float4 x4 = *(const float4*)&xs[(rowLocal0 + r) * 32 + j4 * 4];
                u64 xx;
                xx = pk2(x4.x, x4.x);
                acc[r][0] = ffma2(xx, wA0, acc[r][0]); acc[r][1] = ffma2(xx, wB0, acc[r][1]);
                xx = pk2(x4.y, x4.y);
                acc[r][0] = ffma2(xx, wA1, acc[r][0]); acc[r][1] = ffma2(xx, wB1, acc[r][1]);
                xx = pk2(x4.z, x4.z);
                acc[r][0] = ffma2(xx, wA2, acc[r][0]); acc[r][1] = ffma2(xx, wB2, acc[r][1]);
                xx = pk2(x4.w, x4.w);
                acc[r][0] = ffma2(xx, wA3, acc[r][0]); acc[r][1] = ffma2(xx, wB3, acc[r][1]);
            }
        }
    }

    const float4 b4  = *(const float4*)&bias[c0];
    const float4 gm4 = *(const float4*)&gamma[c0];
    const float4 bt4 = *(const float4*)&beta[c0];
    float ps0 = 0.f, ps1 = 0.f, ps2 = 0.f, ps3 = 0.f;

#pragma unroll
    for (int r = 0; r < 8; r++) {
        int gr = rowG0 + r;
        if (gr < rows) {
            float y0, y1, y2, y3;
            upk2(acc[r][0], y0, y1); upk2(acc[r][1], y2, y3);
            y0 += b4.x; y1 += b4.y; y2 += b4.z; y3 += b4.w;
            float s = y0 + y1 + y2 + y3;
#pragma unroll
            for (int o = 1; o < 16; o <<= 1) s += __shfl_xor_sync(hmask, s, o);
            float mu = s * (1.f / 64.f);
            float d0 = y0 - mu, d1 = y1 - mu, d2 = y2 - mu, d3 = y3 - mu;
            float q = d0 * d0 + d1 * d1 + d2 * d2 + d3 * d3;
#pragma unroll
            for (int o = 1; o < 16; o <<= 1) q += __shfl_xor_sync(hmask, q, o);
            float rs = rsqrtf(q * (1.f / 64.f) + LN_EPS);
            float z0 = d0 * rs * gm4.x + bt4.x;
            float z1 = d1 * rs * gm4.y + bt4.y;
            float z2 = d2 * rs * gm4.z + bt4.z;
            float z3 = d3 * rs * gm4.w + bt4.w;
            z0 = z0 > 0.f ? z0 : 0.2f * z0;
            z1 = z1 > 0.f ? z1 : 0.2f * z1;
            z2 = z2 > 0.f ? z2 : 0.2f * z2;
            z3 = z3 > 0.f ? z3 : 0.2f * z3;
            if (out) *(float4*)&out[(size_t)gr * 64 + c0] = make_float4(z0, z1, z2, z3);
            if (sum_out) { ps0 += z0; ps1 += z1; ps2 += z2; ps3 += z3; }
        }
    }

    if (sum_out) {
        atomicAdd(&ssum[c0 + 0], ps0);
        atomicAdd(&ssum[c0 + 1], ps1);
        atomicAdd(&ssum[c0 + 2], ps2);
        atomicAdd(&ssum[c0 + 3], ps3);
        __syncthreads();
        if (tid < 64) atomicAdd(&sum_out[tid], ssum[tid]);
    }
}

// =====================================================================
// megakernel: [enc2 | enc0 | enc1 | hist | colsum] by blockIdx range.
// All sections independent; FMA-bound encode blocks co-run with
// memory/atomic-bound hist blocks for latency hiding.
// =====================================================================
__global__ void mega_kernel(
    const float* __restrict__ mf0, const float* __restrict__ W0,
    const float* __restrict__ b0, const float* __restrict__ g0, const float* __restrict__ be0,
    const float* __restrict__ mf1, const float* __restrict__ W1,
    const float* __restrict__ b1, const float* __restrict__ g1, const float* __restrict__ be1,
    const float* __restrict__ mf2, const float* __restrict__ W2,
    const float* __restrict__ b2, const float* __restrict__ g2, const float* __restrict__ be2,
    float* __restrict__ m0buf, float* __restrict__ m1buf,
    float* __restrict__ umsum, float* __restrict__ usum,
    const float* __restrict__ user_emb,
    const int* __restrict__ adj_rows, int* __restrict__ cnt)
{
    __shared__ float xs[128 * 32];
    __shared__ float ws[32 * 64];
    __shared__ float ssum[64];

    int b = blockIdx.x;
    if (b < NB_ENC2) {
        encode_body(mf2, W2, b2, g2, be2, nullptr, umsum, N_USERS, 128, b, xs, ws, ssum);
        return;
    }
    b -= NB_ENC2;
    if (b < NB_ENC0) {
        encode_body(mf0, W0, b0, g0, be0, m0buf, nullptr, N_ITEMS, 768, b, xs, ws, ssum);
        return;
    }
    b -= NB_ENC0;
    if (b < NB_ENC1) {
        encode_body(mf1, W1, b1, g1, be1, m1buf, nullptr, N_ITEMS, 384, b, xs, ws, ssum);
        return;
    }
    b -= NB_ENC1;
    if (b < NB_HIST) {
        int e = b * 256 + threadIdx.x;
        if (e < N_EDGES) atomicAdd(&cnt[__ldg(&adj_rows[e])], 1);
        return;
    }
    b -= NB_HIST;
    // colsum of user_emb: 512 rows per block
    {
        int tid = threadIdx.x;
        if (tid < 64) ssum[tid] = 0.f;
        __syncthreads();
        int c = tid & 63;
        int g = tid >> 6;
        int base = b * 512;
        int end = min(base + 512, N_USERS);
        float s = 0.f;
        for (int r = base + g; r < end; r += 4) s += user_emb[(size_t)r * 64 + c];
        atomicAdd(&ssum[c], s);
        __syncthreads();
        if (tid < 64) atomicAdd(&usum[tid], ssum[tid]);
    }
}

// per-item modal attention + weighted combine -> items part buffer Ai
__global__ void attn_kernel(const float* __restrict__ item_emb,
                            const float* __restrict__ W1, const float* __restrict__ b1,
                            const float* __restrict__ W2, const float* __restrict__ b2,
                            const float* __restrict__ usum, const float* __restrict__ umsum,
                            const float* __restrict__ m0buf, const float* __restrict__ m1buf,
                            float* __restrict__ Ai)
{
    int warp = threadIdx.x >> 5;
    int lane = threadIdx.x & 31;
    int i = blockIdx.x * 8 + warp;
    if (i >= N_ITEMS) return;

    const float invU = 1.f / (float)N_USERS;
    float2 u, e;
    u.x = usum[2 * lane] * invU;  u.y = usum[2 * lane + 1] * invU;
    e = *(const float2*)&item_emb[(size_t)i * 64 + 2 * lane];

    u64 h = pk2(0.f, 0.f);
#pragma unroll 8
    for (int j = 0; j < 32; j++) {
        float ua = __shfl_sync(0xFFFFFFFFu, u.x, j);
        float ub = __shfl_sync(0xFFFFFFFFu, u.y, j);
        float2 wA = *(const float2*)&W1[(size_t)(2 * j) * 64 + 2 * lane];
        float2 wB = *(const float2*)&W1[(size_t)(2 * j + 1) * 64 + 2 * lane];
        h = ffma2(pk2(ua, ua), pk2(wA.x, wA.y), h);
        h = ffma2(pk2(ub, ub), pk2(wB.x, wB.y), h);
    }
#pragma unroll 8
    for (int j = 0; j < 32; j++) {
        float ea = __shfl_sync(0xFFFFFFFFu, e.x, j);
        float eb = __shfl_sync(0xFFFFFFFFu, e.y, j);
        float2 wA = *(const float2*)&W1[(size_t)(64 + 2 * j) * 64 + 2 * lane];
        float2 wB = *(const float2*)&W1[(size_t)(64 + 2 * j + 1) * 64 + 2 * lane];
        h = ffma2(pk2(ea, ea), pk2(wA.x, wA.y), h);
        h = ffma2(pk2(eb, eb), pk2(wB.x, wB.y), h);
    }
    float h0, h1;
    upk2(h, h0, h1);
    h0 = tanhf(h0 + b1[2 * lane]);
    h1 = tanhf(h1 + b1[2 * lane + 1]);

    float p0 = h0 * W2[(2 * lane) * 3 + 0] + h1 * W2[(2 * lane + 1) * 3 + 0];
    float p1 = h0 * W2[(2 * lane) * 3 + 1] + h1 * W2[(2 * lane + 1) * 3 + 1];
    float p2 = h0 * W2[(2 * lane) * 3 + 2] + h1 * W2[(2 * lane + 1) * 3 + 2];
#pragma unroll
    for (int o = 1; o < 32; o <<= 1) {
        p0 += __shfl_xor_sync(0xFFFFFFFFu, p0, o);
        p1 += __shfl_xor_sync(0xFFFFFFFFu, p1, o);
        p2 += __shfl_xor_sync(0xFFFFFFFFu, p2, o);
    }
    p0 += b2[0]; p1 += b2[1]; p2 += b2[2];
    float mx = fmaxf(p0, fmaxf(p1, p2));
    float e0 = expf(p0 - mx), e1 = expf(p1 - mx), e2 = expf(p2 - mx);
    float inv = 1.f / (e0 + e1 + e2);
    float w0 = e0 * inv, w1 = e1 * inv, w2 = e2 * inv;

    float2 m0v = *(const float2*)&m0buf[(size_t)i * 64 + 2 * lane];
    float2 m1v = *(const float2*)&m1buf[(size_t)i * 64 + 2 * lane];
    float m2x = umsum[2 * lane] * invU;
    float m2y = umsum[2 * lane + 1] * invU;

    float2 res;
    res.x = e.x + w0 * m0v.x + w1 * m1v.x + w2 * m2x;
    res.y = e.y + w0 * m0v.y + w1 * m1v.y + w2 * m2y;
    *(float2*)&Ai[(size_t)i * 64 + 2 * lane] = res;
}

// ================= CSR build (counting sort by row) =================
__global__ void scan1_kernel(const int* __restrict__ cnt, int* __restrict__ rowptr,
                             int* __restrict__ bsums)
{
    __shared__ int sh[1024];
    int i = blockIdx.x * 1024 + threadIdx.x;
    sh[threadIdx.x] = (i < N_NODES) ? cnt[i] : 0;
    __syncthreads();
#pragma unroll
    for (int off = 1; off < 1024; off <<= 1) {
        int t = (threadIdx.x >= off) ? sh[threadIdx.x - off] : 0;
        __syncthreads();
        sh[threadIdx.x] += t;
        __syncthreads();
    }
    if (i < N_NODES) rowptr[i + 1] = sh[threadIdx.x];
    if (threadIdx.x == 1023) bsums[blockIdx.x] = sh[1023];
}

__global__ void scan2_kernel(int* __restrict__ bsums)
{
    if (threadIdx.x == 0 && blockIdx.x == 0) {
        int acc = 0;
        for (int k = 0; k < NSCAN_BLOCKS; k++) { int t = bsums[k]; bsums[k] = acc; acc += t; }
    }
}

__global__ void scan3_kernel(int* __restrict__ rowptr, const int* __restrict__ bsums)
{
    int i = blockIdx.x * blockDim.x + threadIdx.x;
    if (i < N_NODES) rowptr[i + 1] += bsums[i >> 10];
    if (i == 0) rowptr[0] = 0;
}

__global__ void cursor_kernel(const int* __restrict__ rowptr, int* __restrict__ cur)
{
    int i = blockIdx.x * blockDim.x + threadIdx.x;
    if (i < N_NODES) cur[i] = rowptr[i];
}

__global__ void scatter_kernel(const int* __restrict__ rows, const int* __restrict__ cols,
                               const float* __restrict__ vals,
                               int* __restrict__ cur, int2* __restrict__ epack)
{
    int e = blockIdx.x * blockDim.x + threadIdx.x;
    if (e < N_EDGES) {
        int r = __ldg(&rows[e]);
        int pos = atomicAdd(&cur[r], 1);
        epack[pos] = make_int2(__ldg(&cols[e]), __float_as_int(__ldg(&vals[e])));
    }
}

// virtual all_emb row pointer: users part = user_emb, items part = Ai
__device__ __forceinline__ const float* vrow(const float* __restrict__ user_emb,
                                             const float* __restrict__ Ai, int node)
{
    return (node < N_USERS) ? (user_emb + (size_t)node * 64)
                            : (Ai + (size_t)(node - N_USERS) * 64);
}

// ================= CSR SpMM layer 1: B[row] = sum val * A[col] ==========
__global__ void spmm1_kernel(const float* __restrict__ user_emb, const float* __restrict__ Ai,
                             float* __restrict__ Bm,
                             const int* __restrict__ rowptr, const int2* __restrict__ epack)
{
    int row = blockIdx.x * 16 + (threadIdx.x >> 4);
    if (row >= N_NODES) return;
    const int c = (threadIdx.x & 15) << 2;

    int s = __ldg(&rowptr[row]);
    int e = __ldg(&rowptr[row + 1]);

    float4 acc = make_float4(0.f, 0.f, 0.f, 0.f);
    int j = s;
    for (; j + 1 < e; j += 2) {
        int2 m0 = __ldg(&epack[j]);
        int2 m1 = __ldg(&epack[j + 1]);
        float v0 = __int_as_float(m0.y);
        float v1 = __int_as_float(m1.y);
        float4 x0 = *(const float4*)(vrow(user_emb, Ai, m0.x) + c);
        float4 x1 = *(const float4*)(vrow(user_emb, Ai, m1.x) + c);
        acc.x = fmaf(x0.x, v0, acc.x); acc.y = fmaf(x0.y, v0, acc.y);
        acc.z = fmaf(x0.z, v0, acc.z); acc.w = fmaf(x0.w, v0, acc.w);
        acc.x = fmaf(x1.x, v1, acc.x); acc.y = fmaf(x1.y, v1, acc.y);
        acc.z = fmaf(x1.z, v1, acc.z); acc.w = fmaf(x1.w, v1, acc.w);
    }
    if (j < e) {
        int2 m0 = __ldg(&epack[j]);
        float v0 = __int_as_float(m0.y);
        float4 x0 = *(const float4*)(vrow(user_emb, Ai, m0.x) + c);
        acc.x = fmaf(x0.x, v0, acc.x); acc.y = fmaf(x0.y, v0, acc.y);
        acc.z = fmaf(x0.z, v0, acc.z); acc.w = fmaf(x0.w, v0, acc.w);
    }
    *(float4*)&Bm[(size_t)row * 64 + c] = acc;
}

// ===== CSR SpMM layer 2 fused with finalize: out[row] = (A+B+C)/3 =======
__global__ void spmm2_fin_kernel(const float* __restrict__ user_emb, const float* __restrict__ Ai,
                                 const float* __restrict__ Bm, float* __restrict__ out,
                                 const int* __restrict__ rowptr, const int2* __restrict__ epack)
{
    int row = blockIdx.x * 16 + (threadIdx.x >> 4);
    if (row >= N_NODES) return;
    const int c = (threadIdx.x & 15) << 2;

    int s = __ldg(&rowptr[row]);
    int e = __ldg(&rowptr[row + 1]);

    float4 acc = make_float4(0.f, 0.f, 0.f, 0.f);
    int j = s;
    for (; j + 1 < e; j += 2) {
        int2 m0 = __ldg(&epack[j]);
        int2 m1 = __ldg(&epack[j + 1]);
        float v0 = __int_as_float(m0.y);
        float v1 = __int_as_float(m1.y);
        float4 x0 = *(const float4*)&Bm[(size_t)m0.x * 64 + c];
        float4 x1 = *(const float4*)&Bm[(size_t)m1.x * 64 + c];
        acc.x = fmaf(x0.x, v0, acc.x); acc.y = fmaf(x0.y, v0, acc.y);
        acc.z = fmaf(x0.z, v0, acc.z); acc.w = fmaf(x0.w, v0, acc.w);
        acc.x = fmaf(x1.x, v1, acc.x); acc.y = fmaf(x1.y, v1, acc.y);
        acc.z = fmaf(x1.z, v1, acc.z); acc.w = fmaf(x1.w, v1, acc.w);
    }
    if (j < e) {
        int2 m0 = __ldg(&epack[j]);
        float v0 = __int_as_float(m0.y);
        float4 x0 = *(const float4*)&Bm[(size_t)m0.x * 64 + c];
        acc.x = fmaf(x0.x, v0, acc.x); acc.y = fmaf(x0.y, v0, acc.y);
        acc.z = fmaf(x0.z, v0, acc.z); acc.w = fmaf(x0.w, v0, acc.w);
    }

    float4 a = *(const float4*)(vrow(user_emb, Ai, row) + c);
    float4 b = *(const float4*)&Bm[(size_t)row * 64 + c];
    const float t = 1.f / 3.f;
    *(float4*)&out[(size_t)row * 64 + c] =
        make_float4((a.x + b.x + acc.x) * t, (a.y + b.y + acc.y) * t,
                    (a.z + b.z + acc.z) * t, (a.w + b.w + acc.w) * t);
}

extern "C" void kernel_launch(void* const* d_in, const int* in_sizes, int n_in,
                              void* d_out, int out_size)
{
    const float* user_emb = (const float*)d_in[0];
    const float* item_emb = (const float*)d_in[1];
    const float* mf0 = (const float*)d_in[2];
    const float* mf1 = (const float*)d_in[3];
    const float* mf2 = (const float*)d_in[4];
    const float* W0  = (const float*)d_in[5];
    const float* b0  = (const float*)d_in[6];
    const float* g0  = (const float*)d_in[7];
    const float* be0 = (const float*)d_in[8];
    const float* W1  = (const float*)d_in[9];
    const float* b1  = (const float*)d_in[10];
    const float* g1  = (const float*)d_in[11];
    const float* be1 = (const float*)d_in[12];
    const float* W2  = (const float*)d_in[13];
    const float* b2  = (const float*)d_in[14];
    const float* g2  = (const float*)d_in[15];
    const float* be2 = (const float*)d_in[16];
    const float* aW1 = (const float*)d_in[17];
    const float* ab1 = (const float*)d_in[18];
    const float* aW2 = (const float*)d_in[19];
    const float* ab2 = (const float*)d_in[20];
    const float* adj_vals = (const float*)d_in[21];
    const int*   adj_rows = (const int*)d_in[22];
    const int*   adj_cols = (const int*)d_in[23];

    float *pAi, *pB, *pM0, *pM1, *pUS, *pUM;
    int *pCnt, *pRowptr, *pCur, *pBsums;
    int2 *pEpack;
    cudaGetSymbolAddress((void**)&pAi, g_Ai);
    cudaGetSymbolAddress((void**)&pB, g_B);
    cudaGetSymbolAddress((void**)&pM0, g_m0);
    cudaGetSymbolAddress((void**)&pM1, g_m1);
    cudaGetSymbolAddress((void**)&pUS, g_usum);
    cudaGetSymbolAddress((void**)&pUM, g_umsum);
    cudaGetSymbolAddress((void**)&pCnt, g_cnt);
    cudaGetSymbolAddress((void**)&pRowptr, g_rowptr);
    cudaGetSymbolAddress((void**)&pCur, g_cur);
    cudaGetSymbolAddress((void**)&pBsums, g_bsums);
    cudaGetSymbolAddress((void**)&pEpack, g_epack);

    cudaMemsetAsync(pUS, 0, EMB * sizeof(float));
    cudaMemsetAsync(pUM, 0, EMB * sizeof(float));
    cudaMemsetAsync(pCnt, 0, N_NODES * sizeof(int));

    // encoders + hist + colsum, co-scheduled in one launch
    mega_kernel<<<NB_TOTAL, 256>>>(mf0, W0, b0, g0, be0,
                                   mf1, W1, b1, g1, be1,
                                   mf2, W2, b2, g2, be2,
                                   pM0, pM1, pUM, pUS,
                                   user_emb, adj_rows, pCnt);

    // modal attention -> items part of all_emb
    attn_kernel<<<(N_ITEMS + 7) / 8, 256>>>(item_emb, aW1, ab1, aW2, ab2,
                                            pUS, pUM, pM0, pM1, pAi);

    // CSR build
    scan1_kernel<<<NSCAN_BLOCKS, 1024>>>(pCnt, pRowptr, pBsums);
    scan2_kernel<<<1, 32>>>(pBsums);
    scan3_kernel<<<(N_NODES + 255) / 256, 256>>>(pRowptr, pBsums);
    cursor_kernel<<<(N_NODES + 255) / 256, 256>>>(pRowptr, pCur);
    scatter_kernel<<<(N_EDGES + 255) / 256, 256>>>(adj_rows, adj_cols, adj_vals, pCur, pEpack);

    // 2 propagation layers; layer 2 fused with finalize
    const int spmm_blocks = (N_NODES + 15) / 16;
    spmm1_kernel<<<spmm_blocks, 256>>>(user_emb, pAi, pB, pRowptr, pEpack);
    spmm2_fin_kernel<<<spmm_blocks, 256>>>(user_emb, pAi, pB, (float*)d_out, pRowptr, pEpack);
}

// round 13
// speedup vs baseline: 1.6413x; 1.0010x over previous
#include <cuda_runtime.h>
#include <cuda_bf16.h>
#include <cstdint>

#define N_USERS 100000
#define N_ITEMS 50000
#define N_NODES 150000
#define EMB 64
#define N_EDGES 4000000
#define LN_EPS 1e-5f
#define NSCAN_BLOCKS ((N_NODES + 1023) / 1024)   // 147

// megakernel section sizes
#define NB_ENC2 782    // users encoder, F=128
#define NB_ENC0 391    // items encoder, F=768
#define NB_ENC1 391    // items encoder, F=384
#define NB_HIST 15625  // 4M edges / 256
#define NB_COLSUM 196  // 100000 rows / 512
#define NB_TOTAL (NB_ENC2 + NB_ENC0 + NB_ENC1 + NB_HIST + NB_COLSUM)

typedef unsigned long long u64;

// ---------------- packed f32x2 helpers (sm_103a FFMA2) ----------------
__device__ __forceinline__ u64 pk2(float x, float y) {
    u64 r; asm("mov.b64 %0, {%1, %2};" : "=l"(r) : "f"(x), "f"(y)); return r;
}
__device__ __forceinline__ void upk2(u64 v, float& x, float& y) {
    asm("mov.b64 {%0, %1}, %2;" : "=f"(x), "=f"(y) : "l"(v));
}
__device__ __forceinline__ u64 ffma2(u64 a, u64 b, u64 c) {
    u64 d; asm("fma.rn.f32x2 %0, %1, %2, %3;" : "=l"(d) : "l"(a), "l"(b), "l"(c)); return d;
}

// ---------------- scratch (device globals; no allocation allowed) ----------------
__device__ float g_Ai[N_ITEMS * EMB];    // items part of all_emb (users part = user_emb directly)
__device__ float g_B[N_NODES * EMB];     // spmm layer-1 output
__device__ float g_m0[N_ITEMS * EMB];
__device__ float g_m1[N_ITEMS * EMB];
__device__ float g_usum[EMB];
__device__ float g_umsum[EMB];
// CSR build scratch
__device__ int   g_cnt[N_NODES];
__device__ int   g_rowptr[N_NODES + 1];
__device__ int   g_cur[N_NODES];
__device__ int   g_bsums[NSCAN_BLOCKS];
__device__ int2  g_epack[N_EDGES];       // (col, val-as-int) sorted by row

// =====================================================================
// encode body: out = LeakyReLU(LayerNorm(X @ W + b), 0.2)
// 256 thr, 128 rows/block; half-warp owns 8 rows x (lane-quarter) 4 cols.
// Inner loop: per 4 k-steps -> 12 LDS.128 + 64 FFMA2.
// =====================================================================
__device__ __forceinline__ void encode_body(
    const float* __restrict__ X, const float* __restrict__ W,
    const float* __restrict__ bias, const float* __restrict__ gamma,
    const float* __restrict__ beta,
    float* __restrict__ out, float* __restrict__ sum_out,
    int rows, int F, int blk,
    float* xs /*128*32*/, float* ws /*32*64*/, float* ssum /*64*/)
{
    const int tid  = threadIdx.x;
    if (sum_out && tid < 64) ssum[tid] = 0.f;

    const int warp = tid >> 5;
    const int lane = tid & 31;
    const int half = lane >> 4;
    const int lq   = lane & 15;
    const unsigned hmask = 0xFFFFu << (half * 16);

    const int rowLocal0 = warp * 16 + half * 8;
    const int rowG0     = blk * 128 + rowLocal0;
    const int c0        = lq * 4;

    u64 acc[8][2];
#pragma unroll
    for (int r = 0; r < 8; r++) { acc[r][0] = pk2(0.f, 0.f); acc[r][1] = pk2(0.f, 0.f); }

    for (int kc = 0; kc < F; kc += 32) {
        __syncthreads();
        for (int t = tid; t < 1024; t += 256) {
            int r  = t >> 3;
            int j4 = (t & 7) << 2;
            int gr = blk * 128 + r;
            float4 v = make_float4(0.f, 0.f, 0.f, 0.f);
            if (gr < rows) v = *(const float4*)&X[(size_t)gr * F + kc + j4];
            *(float4*)&xs[r * 32 + j4] = v;
        }
        for (int t = tid; t < 512; t += 256)
            *(float4*)&ws[t * 4] = *(const float4*)&W[(size_t)kc * 64 + t * 4];
        __syncthreads();

#pragma unroll
        for (int j4 = 0; j4 < 8; j4++) {
            float4 w0 = *(const float4*)&ws[(j4 * 4 + 0) * 64 + c0];
            float4 w1 = *(const float4*)&ws[(j4 * 4 + 1) * 64 + c0];
            float4 w2 = *(const float4*)&ws[(j4 * 4 + 2) * 64 + c0];
            float4 w3 = *(const float4*)&ws[(j4 * 4 + 3) * 64 + c0];
            u64 wA0 = pk2(w0.x, w0.y), wB0 = pk2(w0.z, w0.w);
            u64 wA1 = pk2(w1.x, w1.y), wB1 = pk2(w1.z, w1.w);
            u64 wA2 = pk2(w2.x, w2.y), wB2 = pk2(w2.z, w2.w);
            u64 wA3 = pk2(w3.x, w3.y), wB3 = pk2(w3.z, w3.w);
#pragma unroll
            for (int r = 0; r < 8; r++) {
                float4 x4 = *(const float4*)&xs[(rowLocal0 + r) * 32 + j4 * 4];
                u64 xx;
                xx = pk2(x4.x, x4.x);
                acc[r][0] = ffma2(xx, wA0, acc[r][0]); acc[r][1] = ffma2(xx, wB0, acc[r][1]);
                xx = pk2(x4.y, x4.y);
                acc[r][0] = ffma2(xx, wA1, acc[r][0]); acc[r][1] = ffma2(xx, wB1, acc[r][1]);
                xx = pk2(x4.z, x4.z);
                acc[r][0] = ffma2(xx, wA2, acc[r][0]); acc[r][1] = ffma2(xx, wB2, acc[r][1]);
                xx = pk2(x4.w, x4.w);
                acc[r][0] = ffma2(xx, wA3, acc[r][0]); acc[r][1] = ffma2(xx, wB3, acc[r][1]);
            }
        }
    }

    const float4 b4  = *(const float4*)&bias[c0];
    const float4 gm4 = *(const float4*)&gamma[c0];
    const float4 bt4 = *(const float4*)&beta[c0];
    float ps0 = 0.f, ps1 = 0.f, ps2 = 0.f, ps3 = 0.f;

#pragma unroll
    for (int r = 0; r < 8; r++) {
        int gr = rowG0 + r;
        if (gr < rows) {
            float y0, y1, y2, y3;
            upk2(acc[r][0], y0, y1); upk2(acc[r][1], y2, y3);
            y0 += b4.x; y1 += b4.y; y2 += b4.z; y3 += b4.w;
            float s = y0 + y1 + y2 + y3;
#pragma unroll
            for (int o = 1; o < 16; o <<= 1) s += __shfl_xor_sync(hmask, s, o);
            float mu = s * (1.f / 64.f);
            float d0 = y0 - mu, d1 = y1 - mu, d2 = y2 - mu, d3 = y3 - mu;
            float q = d0 * d0 + d1 * d1 + d2 * d2 + d3 * d3;
#pragma unroll
            for (int o = 1; o < 16; o <<= 1) q += __shfl_xor_sync(hmask, q, o);
            float rs = rsqrtf(q * (1.f / 64.f) + LN_EPS);
            float z0 = d0 * rs * gm4.x + bt4.x;
            float z1 = d1 * rs * gm4.y + bt4.y;
            float z2 = d2 * rs * gm4.z + bt4.z;
            float z3 = d3 * rs * gm4.w + bt4.w;
            z0 = z0 > 0.f ? z0 : 0.2f * z0;
            z1 = z1 > 0.f ? z1 : 0.2f * z1;
            z2 = z2 > 0.f ? z2 : 0.2f * z2;
            z3 = z3 > 0.f ? z3 : 0.2f * z3;
            if (out) *(float4*)&out[(size_t)gr * 64 + c0] = make_float4(z0, z1, z2, z3);
            if (sum_out) { ps0 += z0; ps1 += z1; ps2 += z2; ps3 += z3; }
        }
    }

    if (sum_out) {
        atomicAdd(&ssum[c0 + 0], ps0);
        atomicAdd(&ssum[c0 + 1], ps1);
        atomicAdd(&ssum[c0 + 2], ps2);
        atomicAdd(&ssum[c0 + 3], ps3);
        __syncthreads();
        if (tid < 64) atomicAdd(&sum_out[tid], ssum[tid]);
    }
}

// =====================================================================
// megakernel: [enc2 | enc0 | enc1 | hist | colsum] by blockIdx range.
// =====================================================================
__global__ void mega_kernel(
    const float* __restrict__ mf0, const float* __restrict__ W0,
    const float* __restrict__ b0, const float* __restrict__ g0, const float* __restrict__ be0,
    const float* __restrict__ mf1, const float* __restrict__ W1,
    const float* __restrict__ b1, const float* __restrict__ g1, const float* __restrict__ be1,
    const float* __restrict__ mf2, const float* __restrict__ W2,
    const float* __restrict__ b2, const float* __restrict__ g2, const float* __restrict__ be2,
    float* __restrict__ m0buf, float* __restrict__ m1buf,
    float* __restrict__ umsum, float* __restrict__ usum,
    const float* __restrict__ user_emb,
    const int* __restrict__ adj_rows, int* __restrict__ cnt)
{
    __shared__ float xs[128 * 32];
    __shared__ float ws[32 * 64];
    __shared__ float ssum[64];

    int b = blockIdx.x;
    if (b < NB_ENC2) {
        encode_body(mf2, W2, b2, g2, be2, nullptr, umsum, N_USERS, 128, b, xs, ws, ssum);
        return;
    }
    b -= NB_ENC2;
    if (b < NB_ENC0) {
        encode_body(mf0, W0, b0, g0, be0, m0buf, nullptr, N_ITEMS, 768, b, xs, ws, ssum);
        return;
    }
    b -= NB_ENC0;
    if (b < NB_ENC1) {
        encode_body(mf1, W1, b1, g1, be1, m1buf, nullptr, N_ITEMS, 384, b, xs, ws, ssum);
        return;
    }
    b -= NB_ENC1;
    if (b < NB_HIST) {
        int e = b * 256 + threadIdx.x;
        if (e < N_EDGES) atomicAdd(&cnt[__ldg(&adj_rows[e])], 1);
        return;
    }
    b -= NB_HIST;
    // colsum of user_emb: 512 rows per block
    {
        int tid = threadIdx.x;
        if (tid < 64) ssum[tid] = 0.f;
        __syncthreads();
        int c = tid & 63;
        int g = tid >> 6;
        int base = b * 512;
        int end = min(base + 512, N_USERS);
        float s = 0.f;
        for (int r = base + g; r < end; r += 4) s += user_emb[(size_t)r * 64 + c];
        atomicAdd(&ssum[c], s);
        __syncthreads();
        if (tid < 64) atomicAdd(&usum[tid], ssum[tid]);
    }
}

// per-item modal attention + weighted combine -> items part buffer Ai
__global__ void attn_kernel(const float* __restrict__ item_emb,
                            const float* __restrict__ W1, const float* __restrict__ b1,
                            const float* __restrict__ W2, const float* __restrict__ b2,
                            const float* __restrict__ usum, const float* __restrict__ umsum,
                            const float* __restrict__ m0buf, const float* __restrict__ m1buf,
                            float* __restrict__ Ai)
{
    int warp = threadIdx.x >> 5;
    int lane = threadIdx.x & 31;
    int i = blockIdx.x * 8 + warp;
    if (i >= N_ITEMS) return;

    const float invU = 1.f / (float)N_USERS;
    float2 u, e;
    u.x = usum[2 * lane] * invU;  u.y = usum[2 * lane + 1] * invU;
    e = *(const float2*)&item_emb[(size_t)i * 64 + 2 * lane];

    u64 h = pk2(0.f, 0.f);
#pragma unroll 8
    for (int j = 0; j < 32; j++) {
        float ua = __shfl_sync(0xFFFFFFFFu, u.x, j);
        float ub = __shfl_sync(0xFFFFFFFFu, u.y, j);
        float2 wA = *(const float2*)&W1[(size_t)(2 * j) * 64 + 2 * lane];
        float2 wB = *(const float2*)&W1[(size_t)(2 * j + 1) * 64 + 2 * lane];
        h = ffma2(pk2(ua, ua), pk2(wA.x, wA.y), h);
        h = ffma2(pk2(ub, ub), pk2(wB.x, wB.y), h);
    }
#pragma unroll 8
    for (int j = 0; j < 32; j++) {
        float ea = __shfl_sync(0xFFFFFFFFu, e.x, j);
        float eb = __shfl_sync(0xFFFFFFFFu, e.y, j);
        float2 wA = *(const float2*)&W1[(size_t)(64 + 2 * j) * 64 + 2 * lane];
        float2 wB = *(const float2*)&W1[(size_t)(64 + 2 * j + 1) * 64 + 2 * lane];
        h = ffma2(pk2(ea, ea), pk2(wA.x, wA.y), h);
        h = ffma2(pk2(eb, eb), pk2(wB.x, wB.y), h);
    }
    float h0, h1;
    upk2(h, h0, h1);
    h0 = tanhf(h0 + b1[2 * lane]);
    h1 = tanhf(h1 + b1[2 * lane + 1]);

    float p0 = h0 * W2[(2 * lane) * 3 + 0] + h1 * W2[(2 * lane + 1) * 3 + 0];
    float p1 = h0 * W2[(2 * lane) * 3 + 1] + h1 * W2[(2 * lane + 1) * 3 + 1];
    float p2 = h0 * W2[(2 * lane) * 3 + 2] + h1 * W2[(2 * lane + 1) * 3 + 2];
#pragma unroll
    for (int o = 1; o < 32; o <<= 1) {
        p0 += __shfl_xor_sync(0xFFFFFFFFu, p0, o);
        p1 += __shfl_xor_sync(0xFFFFFFFFu, p1, o);
        p2 += __shfl_xor_sync(0xFFFFFFFFu, p2, o);
    }
    p0 += b2[0]; p1 += b2[1]; p2 += b2[2];
    float mx = fmaxf(p0, fmaxf(p1, p2));
    float e0 = expf(p0 - mx), e1 = expf(p1 - mx), e2 = expf(p2 - mx);
    float inv = 1.f / (e0 + e1 + e2);
    float w0 = e0 * inv, w1 = e1 * inv, w2 = e2 * inv;

    float2 m0v = *(const float2*)&m0buf[(size_t)i * 64 + 2 * lane];
    float2 m1v = *(const float2*)&m1buf[(size_t)i * 64 + 2 * lane];
    float m2x = umsum[2 * lane] * invU;
    float m2y = umsum[2 * lane + 1] * invU;

    float2 res;
    res.x = e.x + w0 * m0v.x + w1 * m1v.x + w2 * m2x;
    res.y = e.y + w0 * m0v.y + w1 * m1v.y + w2 * m2y;
    *(float2*)&Ai[(size_t)i * 64 + 2 * lane] = res;
}

// ================= CSR build (counting sort by row) =================
// per-block inclusive scan (1024 elems); writes partial rowptr and block sums
__global__ void scan1_kernel(const int* __restrict__ cnt, int* __restrict__ rowptr,
                             int* __restrict__ bsums)
{
    __shared__ int sh[1024];
    int i = blockIdx.x * 1024 + threadIdx.x;
    sh[threadIdx.x] = (i < N_NODES) ? cnt[i] : 0;
    __syncthreads();
#pragma unroll
    for (int off = 1; off < 1024; off <<= 1) {
        int t = (threadIdx.x >= off) ? sh[threadIdx.x - off] : 0;
        __syncthreads();
        sh[threadIdx.x] += t;
        __syncthreads();
    }
    if (i < N_NODES) rowptr[i + 1] = sh[threadIdx.x];
    if (threadIdx.x == 1023) bsums[blockIdx.x] = sh[1023];
}

// fused: per-block redundant scan of bsums (147 elems) + apply to rowptr +
// write cursor array. Replaces scan2 + scan3 + cursor kernels.
__global__ void scan3f_kernel(int* __restrict__ rowptr, const int* __restrict__ bsums,
                              int* __restrict__ cur)
{
    __shared__ int sh[256];
    const int t = threadIdx.x;
    sh[t] = (t < NSCAN_BLOCKS) ? bsums[t] : 0;
    __syncthreads();
#pragma unroll
    for (int off = 1; off < 256; off <<= 1) {
        int v = (t >= off) ? sh[t - off] : 0;
        __syncthreads();
        sh[t] += v;
        __syncthreads();
    }
    int i = blockIdx.x * 256 + t;
    if (i < N_NODES) {
        int k = i >> 10;
        int ex = (k == 0) ? 0 : sh[k - 1];
        int v = rowptr[i + 1] + ex;
        rowptr[i + 1] = v;
        if (i + 1 < N_NODES) cur[i + 1] = v;   // cur[r] = rowptr[r]
    }
    if (i == 0) { rowptr[0] = 0; cur[0] = 0; }
}

__global__ void scatter_kernel(const int* __restrict__ rows, const int* __restrict__ cols,
                               const float* __restrict__ vals,
                               int* __restrict__ cur, int2* __restrict__ epack)
{
    int e = blockIdx.x * blockDim.x + threadIdx.x;
    if (e < N_EDGES) {
        int r = __ldg(&rows[e]);
        int pos = atomicAdd(&cur[r], 1);
        epack[pos] = make_int2(__ldg(&cols[e]), __float_as_int(__ldg(&vals[e])));
    }
}

// virtual all_emb row pointer: users part = user_emb, items part = Ai
__device__ __forceinline__ const float* vrow(const float* __restrict__ user_emb,
                                             const float* __restrict__ Ai, int node)
{
    return (node < N_USERS) ? (user_emb + (size_t)node * 64)
                            : (Ai + (size_t)(node - N_USERS) * 64);
}

// ================= CSR SpMM layer 1: B[row] = sum val * A[col] ==========
__global__ void spmm1_kernel(const float* __restrict__ user_emb, const float* __restrict__ Ai,
                             float* __restrict__ Bm,
                             const int* __restrict__ rowptr, const int2* __restrict__ epack)
{
    int row = blockIdx.x * 16 + (threadIdx.x >> 4);
    if (row >= N_NODES) return;
    const int c = (threadIdx.x & 15) << 2;

    int s = __ldg(&rowptr[row]);
    int e = __ldg(&rowptr[row + 1]);

    float4 acc = make_float4(0.f, 0.f, 0.f, 0.f);
    int j = s;
    for (; j + 1 < e; j += 2) {
        int2 m0 = __ldg(&epack[j]);
        int2 m1 = __ldg(&epack[j + 1]);
        float v0 = __int_as_float(m0.y);
        float v1 = __int_as_float(m1.y);
        float4 x0 = *(const float4*)(vrow(user_emb, Ai, m0.x) + c);
        float4 x1 = *(const float4*)(vrow(user_emb, Ai, m1.x) + c);
        acc.x = fmaf(x0.x, v0, acc.x); acc.y = fmaf(x0.y, v0, acc.y);
        acc.z = fmaf(x0.z, v0, acc.z); acc.w = fmaf(x0.w, v0, acc.w);
        acc.x = fmaf(x1.x, v1, acc.x); acc.y = fmaf(x1.y, v1, acc.y);
        acc.z = fmaf(x1.z, v1, acc.z); acc.w = fmaf(x1.w, v1, acc.w);
    }
    if (j < e) {
        int2 m0 = __ldg(&epack[j]);
        float v0 = __int_as_float(m0.y);
        float4 x0 = *(const float4*)(vrow(user_emb, Ai, m0.x) + c);
        acc.x = fmaf(x0.x, v0, acc.x); acc.y = fmaf(x0.y, v0, acc.y);
        acc.z = fmaf(x0.z, v0, acc.z); acc.w = fmaf(x0.w, v0, acc.w);
    }
    *(float4*)&Bm[(size_t)row * 64 + c] = acc;
}

// ===== CSR SpMM layer 2 fused with finalize: out[row] = (A+B+C)/3 =======
__global__ void spmm2_fin_kernel(const float* __restrict__ user_emb, const float* __restrict__ Ai,
                                 const float* __restrict__ Bm, float* __restrict__ out,
                                 const int* __restrict__ rowptr, const int2* __restrict__ epack)
{
    int row = blockIdx.x * 16 + (threadIdx.x >> 4);
    if (row >= N_NODES) return;
    const int c = (threadIdx.x & 15) << 2;

    int s = __ldg(&rowptr[row]);
    int e = __ldg(&rowptr[row + 1]);

    float4 acc = make_float4(0.f, 0.f, 0.f, 0.f);
    int j = s;
    for (; j + 1 < e; j += 2) {
        int2 m0 = __ldg(&epack[j]);
        int2 m1 = __ldg(&epack[j + 1]);
        float v0 = __int_as_float(m0.y);
        float v1 = __int_as_float(m1.y);
        float4 x0 = *(const float4*)&Bm[(size_t)m0.x * 64 + c];
        float4 x1 = *(const float4*)&Bm[(size_t)m1.x * 64 + c];
        acc.x = fmaf(x0.x, v0, acc.x); acc.y = fmaf(x0.y, v0, acc.y);
        acc.z = fmaf(x0.z, v0, acc.z); acc.w = fmaf(x0.w, v0, acc.w);
        acc.x = fmaf(x1.x, v1, acc.x); acc.y = fmaf(x1.y, v1, acc.y);
        acc.z = fmaf(x1.z, v1, acc.z); acc.w = fmaf(x1.w, v1, acc.w);
    }
    if (j < e) {
        int2 m0 = __ldg(&epack[j]);
        float v0 = __int_as_float(m0.y);
        float4 x0 = *(const float4*)&Bm[(size_t)m0.x * 64 + c];
        acc.x = fmaf(x0.x, v0, acc.x); acc.y = fmaf(x0.y, v0, acc.y);
        acc.z = fmaf(x0.z, v0, acc.z); acc.w = fmaf(x0.w, v0, acc.w);
    }

    float4 a = *(const float4*)(vrow(user_emb, Ai, row) + c);
    float4 b = *(const float4*)&Bm[(size_t)row * 64 + c];
    const float t = 1.f / 3.f;
    *(float4*)&out[(size_t)row * 64 + c] =
        make_float4((a.x + b.x + acc.x) * t, (a.y + b.y + acc.y) * t,
                    (a.z + b.z + acc.z) * t, (a.w + b.w + acc.w) * t);
}

extern "C" void kernel_launch(void* const* d_in, const int* in_sizes, int n_in,
                              void* d_out, int out_size)
{
    const float* user_emb = (const float*)d_in[0];
    const float* item_emb = (const float*)d_in[1];
    const float* mf0 = (const float*)d_in[2];
    const float* mf1 = (const float*)d_in[3];
    const float* mf2 = (const float*)d_in[4];
    const float* W0  = (const float*)d_in[5];
    const float* b0  = (const float*)d_in[6];
    const float* g0  = (const float*)d_in[7];
    const float* be0 = (const float*)d_in[8];
    const float* W1  = (const float*)d_in[9];
    const float* b1  = (const float*)d_in[10];
    const float* g1  = (const float*)d_in[11];
    const float* be1 = (const float*)d_in[12];
    const float* W2  = (const float*)d_in[13];
    const float* b2  = (const float*)d_in[14];
    const float* g2  = (const float*)d_in[15];
    const float* be2 = (const float*)d_in[16];
    const float* aW1 = (const float*)d_in[17];
    const float* ab1 = (const float*)d_in[18];
    const float* aW2 = (const float*)d_in[19];
    const float* ab2 = (const float*)d_in[20];
    const float* adj_vals = (const float*)d_in[21];
    const int*   adj_rows = (const int*)d_in[22];
    const int*   adj_cols = (const int*)d_in[23];

    float *pAi, *pB, *pM0, *pM1, *pUS, *pUM;
    int *pCnt, *pRowptr, *pCur, *pBsums;
    int2 *pEpack;
    cudaGetSymbolAddress((void**)&pAi, g_Ai);
    cudaGetSymbolAddress((void**)&pB, g_B);
    cudaGetSymbolAddress((void**)&pM0, g_m0);
    cudaGetSymbolAddress((void**)&pM1, g_m1);
    cudaGetSymbolAddress((void**)&pUS, g_usum);
    cudaGetSymbolAddress((void**)&pUM, g_umsum);
    cudaGetSymbolAddress((void**)&pCnt, g_cnt);
    cudaGetSymbolAddress((void**)&pRowptr, g_rowptr);
    cudaGetSymbolAddress((void**)&pCur, g_cur);
    cudaGetSymbolAddress((void**)&pBsums, g_bsums);
    cudaGetSymbolAddress((void**)&pEpack, g_epack);

    cudaMemsetAsync(pUS, 0, EMB * sizeof(float));
    cudaMemsetAsync(pUM, 0, EMB * sizeof(float));
    cudaMemsetAsync(pCnt, 0, N_NODES * sizeof(int));

    // 1. encoders + hist + colsum, co-scheduled in one launch
    mega_kernel<<<NB_TOTAL, 256>>>(mf0, W0, b0, g0, be0,
                                   mf1, W1, b1, g1, be1,
                                   mf2, W2, b2, g2, be2,
                                   pM0, pM1, pUM, pUS,
                                   user_emb, adj_rows, pCnt);

    // 2-3. CSR scan (scan2+scan3+cursor fused into scan3f)
    scan1_kernel<<<NSCAN_BLOCKS, 1024>>>(pCnt, pRowptr, pBsums);
    scan3f_kernel<<<(N_NODES + 255) / 256, 256>>>(pRowptr, pBsums, pCur);

    // 4. edge scatter into CSR order (this is the 4th kernel -> gets profiled)
    scatter_kernel<<<(N_EDGES + 255) / 256, 256>>>(adj_rows, adj_cols, adj_vals, pCur, pEpack);

    // 5. modal attention -> items part of all_emb (only needed before spmm1)
    attn_kernel<<<(N_ITEMS + 7) / 8, 256>>>(item_emb, aW1, ab1, aW2, ab2,
                                            pUS, pUM, pM0, pM1, pAi);

    // 6-7. propagation layers; layer 2 fused with finalize
    const int spmm_blocks = (N_NODES + 15) / 16;
    spmm1_kernel<<<spmm_blocks, 256>>>(user_emb, pAi, pB, pRowptr, pEpack);
    spmm2_fin_kernel<<<spmm_blocks, 256>>>(user_emb, pAi, pB, (float*)d_out, pRowptr, pEpack);
}

// round 16
// speedup vs baseline: 1.6430x; 1.0010x over previous
#include <cuda_runtime.h>
#include <cuda_bf16.h>
#include <cstdint>

#define N_USERS 100000
#define N_ITEMS 50000
#define N_NODES 150000
#define EMB 64
#define N_EDGES 4000000
#define LN_EPS 1e-5f
#define NSCAN_BLOCKS ((N_NODES + 1023) / 1024)   // 147

// megakernel section sizes
#define NB_ENC2 782    // users encoder, F=128
#define NB_ENC0 391    // items encoder, F=768
#define NB_ENC1 391    // items encoder, F=384
#define NB_HIST 15625  // 4M edges / 256
#define NB_COLSUM 196  // 100000 rows / 512
#define NB_TOTAL (NB_ENC2 + NB_ENC0 + NB_ENC1 + NB_HIST + NB_COLSUM)

typedef unsigned long long u64;

// ---------------- packed f32x2 helpers (sm_103a FFMA2) ----------------
__device__ __forceinline__ u64 pk2(float x, float y) {
    u64 r; asm("mov.b64 %0, {%1, %2};" : "=l"(r) : "f"(x), "f"(y)); return r;
}
__device__ __forceinline__ void upk2(u64 v, float& x, float& y) {
    asm("mov.b64 {%0, %1}, %2;" : "=f"(x), "=f"(y) : "l"(v));
}
__device__ __forceinline__ u64 ffma2(u64 a, u64 b, u64 c) {
    u64 d; asm("fma.rn.f32x2 %0, %1, %2, %3;" : "=l"(d) : "l"(a), "l"(b), "l"(c)); return d;
}

// ---------------- scratch (device globals; no allocation allowed) ----------------
__device__ float g_Ai[N_ITEMS * EMB];    // items part of all_emb (users part = user_emb directly)
__device__ float g_B[N_NODES * EMB];     // spmm layer-1 output
__device__ float g_m0[N_ITEMS * EMB];
__device__ float g_m1[N_ITEMS * EMB];
__device__ float g_usum[EMB];
__device__ float g_umsum[EMB];
// CSR build scratch
__device__ int   g_cnt[N_NODES];
__device__ int   g_rank[N_EDGES];        // within-row rank, recorded during hist
__device__ int   g_rowptr[N_NODES + 1];
__device__ int   g_bsums[NSCAN_BLOCKS];
__device__ int2  g_epack[N_EDGES];       // (col, val-as-int) sorted by row

// =====================================================================
// encode body: out = LeakyReLU(LayerNorm(X @ W + b), 0.2)
// =====================================================================
__device__ __forceinline__ void encode_body(
    const float* __restrict__ X, const float* __restrict__ W,
    const float* __restrict__ bias, const float* __restrict__ gamma,
    const float* __restrict__ beta,
    float* __restrict__ out, float* __restrict__ sum_out,
    int rows, int F, int blk,
    float* xs /*128*32*/, float* ws /*32*64*/, float* ssum /*64*/)
{
    const int tid  = threadIdx.x;
    if (sum_out && tid < 64) ssum[tid] = 0.f;

    const int warp = tid >> 5;
    const int lane = tid & 31;
    const int half = lane >> 4;
    const int lq   = lane & 15;
    const unsigned hmask = 0xFFFFu << (half * 16);

    const int rowLocal0 = warp * 16 + half * 8;
    const int rowG0     = blk * 128 + rowLocal0;
    const int c0        = lq * 4;

    u64 acc[8][2];
#pragma unroll
    for (int r = 0; r < 8; r++) { acc[r][0] = pk2(0.f, 0.f); acc[r][1] = pk2(0.f, 0.f); }

    for (int kc = 0; kc < F; kc += 32) {
        __syncthreads();
        for (int t = tid; t < 1024; t += 256) {
            int r  = t >> 3;
            int j4 = (t & 7) << 2;
            int gr = blk * 128 + r;
            float4 v = make_float4(0.f, 0.f, 0.f, 0.f);
            if (gr < rows) v = *(const float4*)&X[(size_t)gr * F + kc + j4];
            *(float4*)&xs[r * 32 + j4] = v;
        }
        for (int t = tid; t < 512; t += 256)
            *(float4*)&ws[t * 4] = *(const float4*)&W[(size_t)kc * 64 + t * 4];
        __syncthreads();

#pragma unroll
        for (int j4 = 0; j4 < 8; j4++) {
            float4 w0 = *(const float4*)&ws[(j4 * 4 + 0) * 64 + c0];
            float4 w1 = *(const float4*)&ws[(j4 * 4 + 1) * 64 + c0];
            float4 w2 = *(const float4*)&ws[(j4 * 4 + 2) * 64 + c0];
            float4 w3 = *(const float4*)&ws[(j4 * 4 + 3) * 64 + c0];
            u64 wA0 = pk2(w0.x, w0.y), wB0 = pk2(w0.z, w0.w);
            u64 wA1 = pk2(w1.x, w1.y), wB1 = pk2(w1.z, w1.w);
            u64 wA2 = pk2(w2.x, w2.y), wB2 = pk2(w2.z, w2.w);
            u64 wA3 = pk2(w3.x, w3.y), wB3 = pk2(w3.z, w3.w);
#pragma unroll
            for (int r = 0; r < 8; r++) {
                float4 x4 = *(const float4*)&xs[(rowLocal0 + r) * 32 + j4 * 4];
                u64 xx;
                xx = pk2(x4.x, x4.x);
                acc[r][0] = ffma2(xx, wA0, acc[r][0]); acc[r][1] = ffma2(xx, wB0, acc[r][1]);
                xx = pk2(x4.y, x4.y);
                acc[r][0] = ffma2(xx, wA1, acc[r][0]); acc[r][1] = ffma2(xx, wB1, acc[r][1]);
                xx = pk2(x4.z, x4.z);
                acc[r][0] = ffma2(xx, wA2, acc[r][0]); acc[r][1] = ffma2(xx, wB2, acc[r][1]);
                xx = pk2(x4.w, x4.w);
                acc[r][0] = ffma2(xx, wA3, acc[r][0]); acc[r][1] = ffma2(xx, wB3, acc[r][1]);
            }
        }
    }

    const float4 b4  = *(const float4*)&bias[c0];
    const float4 gm4 = *(const float4*)&gamma[c0];
    const float4 bt4 = *(const float4*)&beta[c0];
    float ps0 = 0.f, ps1 = 0.f, ps2 = 0.f, ps3 = 0.f;

#pragma unroll
    for (int r = 0; r < 8; r++) {
        int gr = rowG0 + r;
        if (gr < rows) {
            float y0, y1, y2, y3;
            upk2(acc[r][0], y0, y1); upk2(acc[r][1], y2, y3);
            y0 += b4.x; y1 += b4.y; y2 += b4.z; y3 += b4.w;
            float s = y0 + y1 + y2 + y3;
#pragma unroll
            for (int o = 1; o < 16; o <<= 1) s += __shfl_xor_sync(hmask, s, o);
            float mu = s * (1.f / 64.f);
            float d0 = y0 - mu, d1 = y1 - mu, d2 = y2 - mu, d3 = y3 - mu;
            float q = d0 * d0 + d1 * d1 + d2 * d2 + d3 * d3;
#pragma unroll
            for (int o = 1; o < 16; o <<= 1) q += __shfl_xor_sync(hmask, q, o);
            float rs = rsqrtf(q * (1.f / 64.f) + LN_EPS);
            float z0 = d0 * rs * gm4.x + bt4.x;
            float z1 = d1 * rs * gm4.y + bt4.y;
            float z2 = d2 * rs * gm4.z + bt4.z;
            float z3 = d3 * rs * gm4.w + bt4.w;
            z0 = z0 > 0.f ? z0 : 0.2f * z0;
            z1 = z1 > 0.f ? z1 : 0.2f * z1;
            z2 = z2 > 0.f ? z2 : 0.2f * z2;
            z3 = z3 > 0.f ? z3 : 0.2f * z3;
            if (out) *(float4*)&out[(size_t)gr * 64 + c0] = make_float4(z0, z1, z2, z3);
            if (sum_out) { ps0 += z0; ps1 += z1; ps2 += z2; ps3 += z3; }
        }
    }

    if (sum_out) {
        atomicAdd(&ssum[c0 + 0], ps0);
        atomicAdd(&ssum[c0 + 1], ps1);
        atomicAdd(&ssum[c0 + 2], ps2);
        atomicAdd(&ssum[c0 + 3], ps3);
        __syncthreads();
        if (tid < 64) atomicAdd(&sum_out[tid], ssum[tid]);
    }
}

// =====================================================================
// megakernel: [enc2 | enc0 | enc1 | hist+rank | colsum] by blockIdx range.
// hist section records each edge's within-row rank (atomic return value),
// making the later scatter atomic-free.
// =====================================================================
__global__ void mega_kernel(
    const float* __restrict__ mf0, const float* __restrict__ W0,
    const float* __restrict__ b0, const float* __restrict__ g0, const float* __restrict__ be0,
    const float* __restrict__ mf1, const float* __restrict__ W1,
    const float* __restrict__ b1, const float* __restrict__ g1, const float* __restrict__ be1,
    const float* __restrict__ mf2, const float* __restrict__ W2,
    const float* __restrict__ b2, const float* __restrict__ g2, const float* __restrict__ be2,
    float* __restrict__ m0buf, float* __restrict__ m1buf,
    float* __restrict__ umsum, float* __restrict__ usum,
    const float* __restrict__ user_emb,
    const int* __restrict__ adj_rows, int* __restrict__ cnt, int* __restrict__ rank)
{
    __shared__ float xs[128 * 32];
    __shared__ float ws[32 * 64];
    __shared__ float ssum[64];

    int b = blockIdx.x;
    if (b < NB_ENC2) {
        encode_body(mf2, W2, b2, g2, be2, nullptr, umsum, N_USERS, 128, b, xs, ws, ssum);
        return;
    }
    b -= NB_ENC2;
    if (b < NB_ENC0) {
        encode_body(mf0, W0, b0, g0, be0, m0buf, nullptr, N_ITEMS, 768, b, xs, ws, ssum);
        return;
    }
    b -= NB_ENC0;
    if (b < NB_ENC1) {
        encode_body(mf1, W1, b1, g1, be1, m1buf, nullptr, N_ITEMS, 384, b, xs, ws, ssum);
        return;
    }
    b -= NB_ENC1;
    if (b < NB_HIST) {
        int e = b * 256 + threadIdx.x;
        if (e < N_EDGES) {
            int r = __ldg(&adj_rows[e]);
            rank[e] = atomicAdd(&cnt[r], 1);
        }
        return;
    }
    b -= NB_HIST;
    // colsum of user_emb: 512 rows per block
    {
        int tid = threadIdx.x;
        if (tid < 64) ssum[tid] = 0.f;
        __syncthreads();
        int c = tid & 63;
        int g = tid >> 6;
        int base = b * 512;
        int end = min(base + 512, N_USERS);
        float s = 0.f;
        for (int r = base + g; r < end; r += 4) s += user_emb[(size_t)r * 64 + c];
        atomicAdd(&ssum[c], s);
        __syncthreads();
        if (tid < 64) atomicAdd(&usum[tid], ssum[tid]);
    }
}

// per-item modal attention + weighted combine -> items part buffer Ai
__global__ void attn_kernel(const float* __restrict__ item_emb,
                            const float* __restrict__ W1, const float* __restrict__ b1,
                            const float* __restrict__ W2, const float* __restrict__ b2,
                            const float* __restrict__ usum, const float* __restrict__ umsum,
                            const float* __restrict__ m0buf, const float* __restrict__ m1buf,
                            float* __restrict__ Ai)
{
    int warp = threadIdx.x >> 5;
    int lane = threadIdx.x & 31;
    int i = blockIdx.x * 8 + warp;
    if (i >= N_ITEMS) return;

    const float invU = 1.f / (float)N_USERS;
    float2 u, e;
    u.x = usum[2 * lane] * invU;  u.y = usum[2 * lane + 1] * invU;
    e = *(const float2*)&item_emb[(size_t)i * 64 + 2 * lane];

    u64 h = pk2(0.f, 0.f);
#pragma unroll 8
    for (int j = 0; j < 32; j++) {
        float ua = __shfl_sync(0xFFFFFFFFu, u.x, j);
        float ub = __shfl_sync(0xFFFFFFFFu, u.y, j);
        float2 wA = *(const float2*)&W1[(size_t)(2 * j) * 64 + 2 * lane];
        float2 wB = *(const float2*)&W1[(size_t)(2 * j + 1) * 64 + 2 * lane];
        h = ffma2(pk2(ua, ua), pk2(wA.x, wA.y), h);
        h = ffma2(pk2(ub, ub), pk2(wB.x, wB.y), h);
    }
#pragma unroll 8
    for (int j = 0; j < 32; j++) {
        float ea = __shfl_sync(0xFFFFFFFFu, e.x, j);
        float eb = __shfl_sync(0xFFFFFFFFu, e.y, j);
        float2 wA = *(const float2*)&W1[(size_t)(64 + 2 * j) * 64 + 2 * lane];
        float2 wB = *(const float2*)&W1[(size_t)(64 + 2 * j + 1) * 64 + 2 * lane];
        h = ffma2(pk2(ea, ea), pk2(wA.x, wA.y), h);
        h = ffma2(pk2(eb, eb), pk2(wB.x, wB.y), h);
    }
    float h0, h1;
    upk2(h, h0, h1);
    h0 = tanhf(h0 + b1[2 * lane]);
    h1 = tanhf(h1 + b1[2 * lane + 1]);

    float p0 = h0 * W2[(2 * lane) * 3 + 0] + h1 * W2[(2 * lane + 1) * 3 + 0];
    float p1 = h0 * W2[(2 * lane) * 3 + 1] + h1 * W2[(2 * lane + 1) * 3 + 1];
    float p2 = h0 * W2[(2 * lane) * 3 + 2] + h1 * W2[(2 * lane + 1) * 3 + 2];
#pragma unroll
    for (int o = 1; o < 32; o <<= 1) {
        p0 += __shfl_xor_sync(0xFFFFFFFFu, p0, o);
        p1 += __shfl_xor_sync(0xFFFFFFFFu, p1, o);
        p2 += __shfl_xor_sync(0xFFFFFFFFu, p2, o);
    }
    p0 += b2[0]; p1 += b2[1]; p2 += b2[2];
    float mx = fmaxf(p0, fmaxf(p1, p2));
    float e0 = expf(p0 - mx), e1 = expf(p1 - mx), e2 = expf(p2 - mx);
    float inv = 1.f / (e0 + e1 + e2);
    float w0 = e0 * inv, w1 = e1 * inv, w2 = e2 * inv;

    float2 m0v = *(const float2*)&m0buf[(size_t)i * 64 + 2 * lane];
    float2 m1v = *(const float2*)&m1buf[(size_t)i * 64 + 2 * lane];
    float m2x = umsum[2 * lane] * invU;
    float m2y = umsum[2 * lane + 1] * invU;

    float2 res;
    res.x = e.x + w0 * m0v.x + w1 * m1v.x + w2 * m2x;
    res.y = e.y + w0 * m0v.y + w1 * m1v.y + w2 * m2y;
    *(float2*)&Ai[(size_t)i * 64 + 2 * lane] = res;
}

// ================= CSR build =================
// per-block inclusive scan (1024 elems); writes partial rowptr and block sums
__global__ void scan1_kernel(const int* __restrict__ cnt, int* __restrict__ rowptr,
                             int* __restrict__ bsums)
{
    __shared__ int sh[1024];
    int i = blockIdx.x * 1024 + threadIdx.x;
    sh[threadIdx.x] = (i < N_NODES) ? cnt[i] : 0;
    __syncthreads();
#pragma unroll
    for (int off = 1; off < 1024; off <<= 1) {
        int t = (threadIdx.x >= off) ? sh[threadIdx.x - off] : 0;
        __syncthreads();
        sh[threadIdx.x] += t;
        __syncthreads();
    }
    if (i < N_NODES) rowptr[i + 1] = sh[threadIdx.x];
    if (threadIdx.x == 1023) bsums[blockIdx.x] = sh[1023];
}

// fused: per-block redundant scan of bsums (147 elems) + apply to rowptr
__global__ void scan3f_kernel(int* __restrict__ rowptr, const int* __restrict__ bsums)
{
    __shared__ int sh[256];
    const int t = threadIdx.x;
    sh[t] = (t < NSCAN_BLOCKS) ? bsums[t] : 0;
    __syncthreads();
#pragma unroll
    for (int off = 1; off < 256; off <<= 1) {
        int v = (t >= off) ? sh[t - off] : 0;
        __syncthreads();
        sh[t] += v;
        __syncthreads();
    }
    int i = blockIdx.x * 256 + t;
    if (i < N_NODES) {
        int k = i >> 10;
        int ex = (k == 0) ? 0 : sh[k - 1];
        rowptr[i + 1] += ex;
    }
    if (i == 0) rowptr[0] = 0;
}

// atomic-free scatter: pos = rowptr[row] + precomputed rank
__global__ void scatter_kernel(const int* __restrict__ rows, const int* __restrict__ cols,
                               const float* __restrict__ vals, const int* __restrict__ rank,
                               const int* __restrict__ rowptr, int2* __restrict__ epack)
{
    int e = blockIdx.x * blockDim.x + threadIdx.x;
    if (e < N_EDGES) {
        int r = __ldg(&rows[e]);
        int pos = __ldg(&rowptr[r]) + __ldg(&rank[e]);
        epack[pos] = make_int2(__ldg(&cols[e]), __float_as_int(__ldg(&vals[e])));
    }
}

// virtual all_emb row pointer: users part = user_emb, items part = Ai
__device__ __forceinline__ const float* vrow(const float* __restrict__ user_emb,
                                             const float* __restrict__ Ai, int node)
{
    return (node < N_USERS) ? (user_emb + (size_t)node * 64)
                            : (Ai + (size_t)(node - N_USERS) * 64);
}

#define SPMM_ACC(m)                                                     \
    do {                                                                \
        float v = __int_as_float((m).y);                                \
        acc.x = fmaf(xx.x, v, acc.x); acc.y = fmaf(xx.y, v, acc.y);     \
        acc.z = fmaf(xx.z, v, acc.z); acc.w = fmaf(xx.w, v, acc.w);     \
    } while (0)

// ================= CSR SpMM layer 1: B[row] = sum val * A[col] ==========
__global__ void spmm1_kernel(const float* __restrict__ user_emb, const float* __restrict__ Ai,
                             float* __restrict__ Bm,
                             const int* __restrict__ rowptr, const int2* __restrict__ epack)
{
    int row = blockIdx.x * 16 + (threadIdx.x >> 4);
    if (row >= N_NODES) return;
    const int c = (threadIdx.x & 15) << 2;

    int s = __ldg(&rowptr[row]);
    int e = __ldg(&rowptr[row + 1]);

    float4 acc = make_float4(0.f, 0.f, 0.f, 0.f);
    int j = s;
    for (; j + 3 < e; j += 4) {
        int2 m0 = __ldg(&epack[j]);
        int2 m1 = __ldg(&epack[j + 1]);
        int2 m2 = __ldg(&epack[j + 2]);
        int2 m3 = __ldg(&epack[j + 3]);
        float4 x0 = *(const float4*)(vrow(user_emb, Ai, m0.x) + c);
        float4 x1 = *(const float4*)(vrow(user_emb, Ai, m1.x) + c);
        float4 x2 = *(const float4*)(vrow(user_emb, Ai, m2.x) + c);
        float4 x3 = *(const float4*)(vrow(user_emb, Ai, m3.x) + c);
        { float4 xx = x0; SPMM_ACC(m0); }
        { float4 xx = x1; SPMM_ACC(m1); }
        { float4 xx = x2; SPMM_ACC(m2); }
        { float4 xx = x3; SPMM_ACC(m3); }
    }
    for (; j < e; j++) {
        int2 m0 = __ldg(&epack[j]);
        float4 xx = *(const float4*)(vrow(user_emb, Ai, m0.x) + c);
        SPMM_ACC(m0);
    }
    *(float4*)&Bm[(size_t)row * 64 + c] = acc;
}

// ===== CSR SpMM layer 2 fused with finalize: out[row] = (A+B+C)/3 =======
__global__ void spmm2_fin_kernel(const float* __restrict__ user_emb, const float* __restrict__ Ai,
                                 const float* __restrict__ Bm, float* __restrict__ out,
                                 const int* __restrict__ rowptr, const int2* __restrict__ epack)
{
    int row = blockIdx.x * 16 + (threadIdx.x >> 4);
    if (row >= N_NODES) return;
    const int c = (threadIdx.x & 15) << 2;

    int s = __ldg(&rowptr[row]);
    int e = __ldg(&rowptr[row + 1]);

    float4 acc = make_float4(0.f, 0.f, 0.f, 0.f);
    int j = s;
    for (; j + 3 < e; j += 4) {
        int2 m0 = __ldg(&epack[j]);
        int2 m1 = __ldg(&epack[j + 1]);
        int2 m2 = __ldg(&epack[j + 2]);
        int2 m3 = __ldg(&epack[j + 3]);
        float4 x0 = *(const float4*)&Bm[(size_t)m0.x * 64 + c];
        float4 x1 = *(const float4*)&Bm[(size_t)m1.x * 64 + c];
        float4 x2 = *(const float4*)&Bm[(size_t)m2.x * 64 + c];
        float4 x3 = *(const float4*)&Bm[(size_t)m3.x * 64 + c];
        { float4 xx = x0; SPMM_ACC(m0); }
        { float4 xx = x1; SPMM_ACC(m1); }
        { float4 xx = x2; SPMM_ACC(m2); }
        { float4 xx = x3; SPMM_ACC(m3); }
    }
    for (; j < e; j++) {
        int2 m0 = __ldg(&epack[j]);
        float4 xx = *(const float4*)&Bm[(size_t)m0.x * 64 + c];
        SPMM_ACC(m0);
    }

    float4 a = *(const float4*)(vrow(user_emb, Ai, row) + c);
    float4 b = *(const float4*)&Bm[(size_t)row * 64 + c];
    const float t = 1.f / 3.f;
    *(float4*)&out[(size_t)row * 64 + c] =
        make_float4((a.x + b.x + acc.x) * t, (a.y + b.y + acc.y) * t,
                    (a.z + b.z + acc.z) * t, (a.w + b.w + acc.w) * t);
}

extern "C" void kernel_launch(void* const* d_in, const int* in_sizes, int n_in,
                              void* d_out, int out_size)
{
    const float* user_emb = (const float*)d_in[0];
    const float* item_emb = (const float*)d_in[1];
    const float* mf0 = (const float*)d_in[2];
    const float* mf1 = (const float*)d_in[3];
    const float* mf2 = (const float*)d_in[4];
    const float* W0  = (const float*)d_in[5];
    const float* b0  = (const float*)d_in[6];
    const float* g0  = (const float*)d_in[7];
    const float* be0 = (const float*)d_in[8];
    const float* W1  = (const float*)d_in[9];
    const float* b1  = (const float*)d_in[10];
    const float* g1  = (const float*)d_in[11];
    const float* be1 = (const float*)d_in[12];
    const float* W2  = (const float*)d_in[13];
    const float* b2  = (const float*)d_in[14];
    const float* g2  = (const float*)d_in[15];
    const float* be2 = (const float*)d_in[16];
    const float* aW1 = (const float*)d_in[17];
    const float* ab1 = (const float*)d_in[18];
    const float* aW2 = (const float*)d_in[19];
    const float* ab2 = (const float*)d_in[20];
    const float* adj_vals = (const float*)d_in[21];
    const int*   adj_rows = (const int*)d_in[22];
    const int*   adj_cols = (const int*)d_in[23];

    float *pAi, *pB, *pM0, *pM1, *pUS, *pUM;
    int *pCnt, *pRank, *pRowptr, *pBsums;
    int2 *pEpack;
    cudaGetSymbolAddress((void**)&pAi, g_Ai);
    cudaGetSymbolAddress((void**)&pB, g_B);
    cudaGetSymbolAddress((void**)&pM0, g_m0);
    cudaGetSymbolAddress((void**)&pM1, g_m1);
    cudaGetSymbolAddress((void**)&pUS, g_usum);
    cudaGetSymbolAddress((void**)&pUM, g_umsum);
    cudaGetSymbolAddress((void**)&pCnt, g_cnt);
    cudaGetSymbolAddress((void**)&pRank, g_rank);
    cudaGetSymbolAddress((void**)&pRowptr, g_rowptr);
    cudaGetSymbolAddress((void**)&pBsums, g_bsums);
    cudaGetSymbolAddress((void**)&pEpack, g_epack);

    cudaMemsetAsync(pUS, 0, EMB * sizeof(float));
    cudaMemsetAsync(pUM, 0, EMB * sizeof(float));
    cudaMemsetAsync(pCnt, 0, N_NODES * sizeof(int));

    // 1. encoders + hist(+rank) + colsum, co-scheduled in one launch
    mega_kernel<<<NB_TOTAL, 256>>>(mf0, W0, b0, g0, be0,
                                   mf1, W1, b1, g1, be1,
                                   mf2, W2, b2, g2, be2,
                                   pM0, pM1, pUM, pUS,
                                   user_emb, adj_rows, pCnt, pRank);

    // 2-3. CSR scan
    scan1_kernel<<<NSCAN_BLOCKS, 1024>>>(pCnt, pRowptr, pBsums);
    scan3f_kernel<<<(N_NODES + 255) / 256, 256>>>(pRowptr, pBsums);

    // 4. atomic-free edge scatter into CSR order (profiled launch)
    scatter_kernel<<<(N_EDGES + 255) / 256, 256>>>(adj_rows, adj_cols, adj_vals,
                                                   pRank, pRowptr, pEpack);

    // 5. modal attention -> items part of all_emb
    attn_kernel<<<(N_ITEMS + 7) / 8, 256>>>(item_emb, aW1, ab1, aW2, ab2,
                                            pUS, pUM, pM0, pM1, pAi);

    // 6-7. propagation layers; layer 2 fused with finalize
    const int spmm_blocks = (N_NODES + 15) / 16;
    spmm1_kernel<<<spmm_blocks, 256>>>(user_emb, pAi, pB, pRowptr, pEpack);
    spmm2_fin_kernel<<<spmm_blocks, 256>>>(user_emb, pAi, pB, (float*)d_out, pRowptr, pEpack);
}